// round 16
// baseline (speedup 1.0000x reference)
#include <cuda_runtime.h>
#include <math.h>
#include <stdint.h>

#define Nn    20000
#define Ee    320000
#define FIN   128
#define H1c   64
#define H2c   128
#define HEADSc 8
#define NCc   40
#define K1c   16000
#define K2c   12800

#define CDIV(a,b) (((a)+(b)-1)/(b))

// ---------------------------------------------------------------------------
// Device scratch
// ---------------------------------------------------------------------------
__device__ float d_aggr[K1c*H1c];
__device__ int   d_cnt[Nn];
__device__ int   d_rowptr[Nn+1];
__device__ int   d_wp[Nn];
__device__ int   d_csr[Ee];
__device__ float d_gP[Nn*H2c];
__device__ float d_gQR[Nn*3*H1c > Nn*2*H2c ? Nn*3*H1c : Nn*2*H2c];
__device__ float d_h1[Nn*H1c];
__device__ float d_hp1[K1c*H1c];
__device__ float d_h2[K1c*H2c];
__device__ float d_hp2[K2c*H2c];
__device__ float d_z[K2c*HEADSc*H2c];      // 12800 x 1024 aggregated hp2-space
__device__ float d_wt[HEADSc*H2c*H2c];     // 1024 x 128 reshaped gat weight
__device__ float d_va[FIN*16];
__device__ float d_alad[K2c*16];
__device__ float d_att[Ee*HEADSc];
__device__ float d_attself[K2c*HEADSc];
__device__ float d_gin[K2c*H2c];
__device__ float d_y1[K2c*H1c];
__device__ float d_o1[K2c*H1c];
__device__ float d_acc[K2c];               // out-edge dinv sums
__device__ float d_rvec[H1c];              // wsum^T @ o1
__device__ float d_dinv[K2c];
__device__ float d_score[Nn];
__device__ int   d_keep[Nn];
__device__ int   d_nid[Nn];
__device__ int   d_src1[Ee], d_dst1[Ee], d_src2[Ee], d_dst2[Ee];
__device__ int   d_Ecnt[2];

// ---------------------------------------------------------------------------
// CSR build
// ---------------------------------------------------------------------------
__global__ void k_count(const int* __restrict__ dst, int* __restrict__ cnt,
                        const int* pE, int Emax){
    int e = blockIdx.x*blockDim.x + threadIdx.x;
    if (e >= Emax) return;
    int E = pE ? *pE : Emax;
    if (e < E) atomicAdd(&cnt[dst[e]], 1);
}

__device__ __forceinline__ int blk_scan_incl(int v, int tid, int* warpsum, int* total){
    __syncthreads();
    int lane = tid & 31, wid = tid >> 5;
    #pragma unroll
    for (int o = 1; o < 32; o <<= 1) {
        int t = __shfl_up_sync(0xFFFFFFFFu, v, o);
        if (lane >= o) v += t;
    }
    if (lane == 31) warpsum[wid] = v;
    __syncthreads();
    if (wid == 0) {
        int s = warpsum[lane];
        #pragma unroll
        for (int o = 1; o < 32; o <<= 1) {
            int t = __shfl_up_sync(0xFFFFFFFFu, s, o);
            if (lane >= o) s += t;
        }
        warpsum[lane] = s;
    }
    __syncthreads();
    *total = warpsum[31];
    return v + (wid ? warpsum[wid-1] : 0);
}

// single-block SINGLE-SWEEP exclusive scan: all loads upfront (MLP), one block
// scan, one emit. Zeroes deg[0..n) after reading; optional dinv emit.
// n % 4 == 0, n <= 20480.
__global__ void k_exscan(int* __restrict__ deg, int* __restrict__ rowptr,
                         int* __restrict__ wp, int n,
                         float* __restrict__ dinvOut){
    __shared__ int warpsum[32];
    int tid = threadIdx.x;                  // 1024 threads
    int nq = n >> 2;                        // int4 count
    int per = (nq + 1023) >> 10;            // int4s per thread (<=5)
    int q0 = tid * per;
    int4 v[5];
    #pragma unroll
    for (int j = 0; j < 5; j++) {
        v[j] = make_int4(0,0,0,0);
        if (j < per) {
            int q = q0 + j;
            if (q < nq) v[j] = *reinterpret_cast<const int4*>(deg + q*4);
        }
    }
    int s = 0;
    #pragma unroll
    for (int j = 0; j < 5; j++) s += v[j].x + v[j].y + v[j].z + v[j].w;
    int tot;
    int incl = blk_scan_incl(s, tid, warpsum, &tot);
    int run = incl - s;
    #pragma unroll
    for (int j = 0; j < 5; j++) {
        if (j < per) {
            int q = q0 + j;
            if (q < nq) {
                int i0 = q*4;
                rowptr[i0]   = run; wp[i0]   = run;
                if (dinvOut) dinvOut[i0]   = rsqrtf((float)(v[j].x + 1));
                run += v[j].x;
                rowptr[i0+1] = run; wp[i0+1] = run;
                if (dinvOut) dinvOut[i0+1] = rsqrtf((float)(v[j].y + 1));
                run += v[j].y;
                rowptr[i0+2] = run; wp[i0+2] = run;
                if (dinvOut) dinvOut[i0+2] = rsqrtf((float)(v[j].z + 1));
                run += v[j].z;
                rowptr[i0+3] = run; wp[i0+3] = run;
                if (dinvOut) dinvOut[i0+3] = rsqrtf((float)(v[j].w + 1));
                run += v[j].w;
                *reinterpret_cast<int4*>(deg + i0) = make_int4(0,0,0,0);
            }
        }
    }
    if (tid == 0) rowptr[n] = tot;
}

__global__ void k_fill(const int* __restrict__ src, const int* __restrict__ dst,
                       int* __restrict__ wp, int* __restrict__ csr,
                       const int* pE, int Emax){
    int e = blockIdx.x*blockDim.x + threadIdx.x;
    if (e >= Emax) return;
    int E = pE ? *pE : Emax;
    if (e >= E) return;
    int d = dst[e];
    int p = atomicAdd(&wp[d], 1);
    csr[p] = src[e];
}

// ---------------------------------------------------------------------------
// SAGE gathers (fused score output)
// ---------------------------------------------------------------------------
// SAGE1: h = relu(mean_nb(Y[:,0:64]) + Y[w,64:128] + bl) + Y[w,128:192] + rb
// plus fused: score[w] = tanh((h . pw) / ||pw||)
__global__ void k_sage1_gather(const int* __restrict__ rowptr, const int* __restrict__ csr,
                               const float* __restrict__ Y,
                               const float* __restrict__ bl, const float* __restrict__ rb,
                               const float* __restrict__ pw,
                               float* __restrict__ h, float* __restrict__ score, int n){
    int t = blockIdx.x*blockDim.x + threadIdx.x;
    int w = t >> 5, lane = t & 31;
    if (w >= n) return;
    // per-warp wnorm (64 floats, L1-resident)
    float w0 = pw[lane], w1 = pw[32 + lane];
    float wn = w0*w0 + w1*w1;
    #pragma unroll
    for (int o = 16; o; o >>= 1) wn += __shfl_down_sync(0xFFFFFFFFu, wn, o);
    float wni = rsqrtf(__shfl_sync(0xFFFFFFFFu, wn, 0));

    int e0 = rowptr[w], e1 = rowptr[w+1];
    float a0 = 0.f, a1 = 0.f;
    for (int p = e0; p < e1; p++) {
        const float* yr = Y + (size_t)csr[p]*192;
        a0 += yr[lane];
        a1 += yr[32 + lane];
    }
    float inv = 1.f / fmaxf((float)(e1 - e0), 1.f);
    a0 *= inv; a1 *= inv;
    const float* yw = Y + (size_t)w*192;
    float hv0 = fmaxf(a0 + yw[64+lane] + bl[lane],    0.f) + yw[128+lane] + rb[lane];
    float hv1 = fmaxf(a1 + yw[96+lane] + bl[32+lane], 0.f) + yw[160+lane] + rb[32+lane];
    h[w*H1c + lane]      = hv0;
    h[w*H1c + 32 + lane] = hv1;
    float d = hv0*w0 + hv1*w1;
    #pragma unroll
    for (int o = 16; o; o >>= 1) d += __shfl_down_sync(0xFFFFFFFFu, d, o);
    if (!lane) score[w] = tanhf(d * wni);
}

__global__ void k_mean_gather(const int* __restrict__ rowptr, const int* __restrict__ csr,
                              const float* __restrict__ x, float* __restrict__ out, int n){
    int t = blockIdx.x*blockDim.x + threadIdx.x;
    int w = t >> 5, lane = t & 31;
    if (w >= n) return;
    int e0 = rowptr[w], e1 = rowptr[w+1];
    float a0 = 0.f, a1 = 0.f;
    for (int p = e0; p < e1; p++) {
        int s = csr[p];
        a0 += x[s*H1c + lane];
        a1 += x[s*H1c + 32 + lane];
    }
    float inv = 1.f / fmaxf((float)(e1 - e0), 1.f);
    out[w*H1c + lane]      = a0 * inv;
    out[w*H1c + 32 + lane] = a1 * inv;
}

// SAGE2 combine (warp per node) with fused score:
// h = relu(P + QR[:, :128] + bl) + QR[:, 128:] + rb; score = tanh((h.pw)/||pw||)
__global__ void k_sage2_combine(const float* __restrict__ P, const float* __restrict__ QR,
                                const float* __restrict__ bl, const float* __restrict__ rb,
                                const float* __restrict__ pw,
                                float* __restrict__ h, float* __restrict__ score, int n){
    int t = blockIdx.x*blockDim.x + threadIdx.x;
    int w = t >> 5, lane = t & 31;
    if (w >= n) return;
    float w0 = pw[lane], w1 = pw[lane+32], w2 = pw[lane+64], w3 = pw[lane+96];
    float wn = w0*w0 + w1*w1 + w2*w2 + w3*w3;
    #pragma unroll
    for (int o = 16; o; o >>= 1) wn += __shfl_down_sync(0xFFFFFFFFu, wn, o);
    float wni = rsqrtf(__shfl_sync(0xFFFFFFFFu, wn, 0));

    const float* pr = P + (size_t)w*H2c;
    const float* qr = QR + (size_t)w*2*H2c;
    float* hw = h + (size_t)w*H2c;
    float v0 = fmaxf(pr[lane]    + qr[lane]    + bl[lane],    0.f) + qr[H2c+lane]    + rb[lane];
    float v1 = fmaxf(pr[lane+32] + qr[lane+32] + bl[lane+32], 0.f) + qr[H2c+lane+32] + rb[lane+32];
    float v2 = fmaxf(pr[lane+64] + qr[lane+64] + bl[lane+64], 0.f) + qr[H2c+lane+64] + rb[lane+64];
    float v3 = fmaxf(pr[lane+96] + qr[lane+96] + bl[lane+96], 0.f) + qr[H2c+lane+96] + rb[lane+96];
    hw[lane] = v0; hw[lane+32] = v1; hw[lane+64] = v2; hw[lane+96] = v3;
    float d = v0*w0;
    d += v1*w1; d += v2*w2; d += v3*w3;
    #pragma unroll
    for (int o = 16; o; o >>= 1) d += __shfl_down_sync(0xFFFFFFFFu, d, o);
    if (!lane) score[w] = tanhf(d * wni);
}

// ---------------------------------------------------------------------------
// SGEMM (fp32): C = A@B, 128x128 tile, BK=16, double-buffered, 8x8/thread.
// ---------------------------------------------------------------------------
#define GBM 128
#define GBN 128
#define GBK 16
__device__ __forceinline__ float bsel_load(const float* __restrict__ B,
                                           const float* __restrict__ B2,
                                           const float* __restrict__ B3,
                                           int gk, int gc, int N, int Nh){
    if (gc >= N) return 0.f;
    if (!B2) return B[(size_t)gk*N + gc];
    if (gc < Nh) return B[(size_t)gk*Nh + gc];
    if (!B3 || gc < 2*Nh) return B2[(size_t)gk*Nh + gc - Nh];
    return B3[(size_t)gk*Nh + gc - 2*Nh];
}

__global__ void __launch_bounds__(256)
k_gemm(const float* __restrict__ A, const float* __restrict__ B,
       const float* __restrict__ B2, const float* __restrict__ B3,
       float* __restrict__ C, int M, int N, int K, int Nh,
       const float* __restrict__ ebias, const float* __restrict__ eres, int erelu){
    __shared__ float As[2][GBK][GBM+4];
    __shared__ float Bs[2][GBK][GBN];
    int tid = threadIdx.x;                    // 256 threads
    int rowBase = blockIdx.y*GBM, colBase = blockIdx.x*GBN;
    int tr = tid >> 4, tc = tid & 15;
    int ar = tid >> 1, kseg = (tid & 1) * 8;
    int br = tid >> 4, bc0 = (tid & 15) * 8;
    float acc[8][8];
    #pragma unroll
    for (int i = 0; i < 8; i++)
        #pragma unroll
        for (int j = 0; j < 8; j++) acc[i][j] = 0.f;

    int nk = K / GBK;
    float4 pa0, pa1; float pb[8];
    {
        int gr = rowBase + ar;
        pa0 = make_float4(0.f,0.f,0.f,0.f); pa1 = pa0;
        if (gr < M) {
            pa0 = *reinterpret_cast<const float4*>(&A[(size_t)gr*K + kseg]);
            pa1 = *reinterpret_cast<const float4*>(&A[(size_t)gr*K + kseg + 4]);
        }
        #pragma unroll
        for (int j = 0; j < 8; j++)
            pb[j] = bsel_load(B, B2, B3, br, colBase + bc0 + j, N, Nh);
    }
    As[0][kseg+0][ar]=pa0.x; As[0][kseg+1][ar]=pa0.y; As[0][kseg+2][ar]=pa0.z; As[0][kseg+3][ar]=pa0.w;
    As[0][kseg+4][ar]=pa1.x; As[0][kseg+5][ar]=pa1.y; As[0][kseg+6][ar]=pa1.z; As[0][kseg+7][ar]=pa1.w;
    #pragma unroll
    for (int j = 0; j < 8; j++) Bs[0][br][bc0+j] = pb[j];
    __syncthreads();

    for (int kt = 0; kt < nk; kt++) {
        int cur = kt & 1;
        if (kt + 1 < nk) {
            int k0 = (kt+1)*GBK;
            int gr = rowBase + ar;
            pa0 = make_float4(0.f,0.f,0.f,0.f); pa1 = pa0;
            if (gr < M) {
                pa0 = *reinterpret_cast<const float4*>(&A[(size_t)gr*K + k0 + kseg]);
                pa1 = *reinterpret_cast<const float4*>(&A[(size_t)gr*K + k0 + kseg + 4]);
            }
            #pragma unroll
            for (int j = 0; j < 8; j++)
                pb[j] = bsel_load(B, B2, B3, k0 + br, colBase + bc0 + j, N, Nh);
        }
        #pragma unroll
        for (int kk = 0; kk < GBK; kk++) {
            float a[8], b[8];
            #pragma unroll
            for (int i = 0; i < 4; i++) { a[i] = As[cur][kk][tr*4+i]; a[4+i] = As[cur][kk][64+tr*4+i]; }
            #pragma unroll
            for (int j = 0; j < 4; j++) { b[j] = Bs[cur][kk][tc*4+j]; b[4+j] = Bs[cur][kk][64+tc*4+j]; }
            #pragma unroll
            for (int i = 0; i < 8; i++)
                #pragma unroll
                for (int j = 0; j < 8; j++) acc[i][j] += a[i]*b[j];
        }
        if (kt + 1 < nk) {
            int nb = 1 - cur;
            As[nb][kseg+0][ar]=pa0.x; As[nb][kseg+1][ar]=pa0.y; As[nb][kseg+2][ar]=pa0.z; As[nb][kseg+3][ar]=pa0.w;
            As[nb][kseg+4][ar]=pa1.x; As[nb][kseg+5][ar]=pa1.y; As[nb][kseg+6][ar]=pa1.z; As[nb][kseg+7][ar]=pa1.w;
            #pragma unroll
            for (int j = 0; j < 8; j++) Bs[nb][br][bc0+j] = pb[j];
        }
        __syncthreads();
    }
    #pragma unroll
    for (int i = 0; i < 8; i++) {
        int r = rowBase + ((i < 4) ? (tr*4 + i) : (64 + tr*4 + i - 4));
        if (r >= M) continue;
        #pragma unroll
        for (int j = 0; j < 8; j++) {
            int c = colBase + ((j < 4) ? (tc*4 + j) : (64 + tc*4 + j - 4));
            if (c >= N) continue;
            float v = acc[i][j];
            if (ebias) {
                v += ebias[c];
                if (erelu) v = fmaxf(v, 0.f);
                if (eres) v += eres[(size_t)r*N + c];
            }
            C[(size_t)r*N + c] = v;
        }
    }
}

// ---------------------------------------------------------------------------
// TF32 tensor-core GEMM (Z@wt): C = relu(A@B + ebias) + eres.
// M%128==0, N==128, K%16==0.
// ---------------------------------------------------------------------------
__device__ __forceinline__ unsigned f2tf32(float f){
    unsigned r;
    asm("cvt.rna.tf32.f32 %0, %1;" : "=r"(r) : "f"(f));
    return r;
}

__global__ void __launch_bounds__(256)
k_gemm_tf32(const float* __restrict__ A, const float* __restrict__ B,
            float* __restrict__ C, int M, int N, int K,
            const float* __restrict__ ebias, const float* __restrict__ eres){
    __shared__ float As[2][16][132];
    __shared__ float Bs[2][16][132];
    int tid = threadIdx.x;                 // 256 threads = 8 warps (2m x 4n)
    int lane = tid & 31, warp = tid >> 5;
    int wm = (warp & 1) * 64;
    int wn = (warp >> 1) * 32;
    int rowBase = blockIdx.y*128, colBase = blockIdx.x*128;
    int ar = tid >> 1, kseg = (tid & 1) * 8;
    int br = tid >> 4, bc0 = (tid & 15) * 8;
    int gq = lane >> 2, tg = lane & 3;
    float acc[4][4][4];
    #pragma unroll
    for (int i=0;i<4;i++)
        #pragma unroll
        for (int j=0;j<4;j++)
            #pragma unroll
            for (int q=0;q<4;q++) acc[i][j][q]=0.f;

    int nk = K / 16;
    float4 pa0, pa1, pb0, pb1;
    {
        const float* Ar = A + (size_t)(rowBase+ar)*K + kseg;
        pa0 = *reinterpret_cast<const float4*>(Ar);
        pa1 = *reinterpret_cast<const float4*>(Ar + 4);
        const float* Br = B + (size_t)br*N + colBase + bc0;
        pb0 = *reinterpret_cast<const float4*>(Br);
        pb1 = *reinterpret_cast<const float4*>(Br + 4);
    }
    As[0][kseg+0][ar]=pa0.x; As[0][kseg+1][ar]=pa0.y; As[0][kseg+2][ar]=pa0.z; As[0][kseg+3][ar]=pa0.w;
    As[0][kseg+4][ar]=pa1.x; As[0][kseg+5][ar]=pa1.y; As[0][kseg+6][ar]=pa1.z; As[0][kseg+7][ar]=pa1.w;
    Bs[0][br][bc0+0]=pb0.x; Bs[0][br][bc0+1]=pb0.y; Bs[0][br][bc0+2]=pb0.z; Bs[0][br][bc0+3]=pb0.w;
    Bs[0][br][bc0+4]=pb1.x; Bs[0][br][bc0+5]=pb1.y; Bs[0][br][bc0+6]=pb1.z; Bs[0][br][bc0+7]=pb1.w;
    __syncthreads();

    for (int kt = 0; kt < nk; kt++) {
        int cur = kt & 1;
        if (kt + 1 < nk) {
            int k0 = (kt+1)*16;
            const float* Ar = A + (size_t)(rowBase+ar)*K + k0 + kseg;
            pa0 = *reinterpret_cast<const float4*>(Ar);
            pa1 = *reinterpret_cast<const float4*>(Ar + 4);
            const float* Br = B + (size_t)(k0+br)*N + colBase + bc0;
            pb0 = *reinterpret_cast<const float4*>(Br);
            pb1 = *reinterpret_cast<const float4*>(Br + 4);
        }
        #pragma unroll
        for (int k8 = 0; k8 < 16; k8 += 8) {
            unsigned a[4][4], b[4][2];
            #pragma unroll
            for (int i = 0; i < 4; i++) {
                int mr = wm + i*16 + gq;
                a[i][0] = f2tf32(As[cur][k8+tg][mr]);
                a[i][1] = f2tf32(As[cur][k8+tg][mr+8]);
                a[i][2] = f2tf32(As[cur][k8+4+tg][mr]);
                a[i][3] = f2tf32(As[cur][k8+4+tg][mr+8]);
            }
            #pragma unroll
            for (int j = 0; j < 4; j++) {
                int nc = wn + j*8 + gq;
                b[j][0] = f2tf32(Bs[cur][k8+tg][nc]);
                b[j][1] = f2tf32(Bs[cur][k8+4+tg][nc]);
            }
            #pragma unroll
            for (int i = 0; i < 4; i++)
                #pragma unroll
                for (int j = 0; j < 4; j++) {
                    asm volatile(
                        "mma.sync.aligned.m16n8k8.row.col.f32.tf32.tf32.f32 "
                        "{%0,%1,%2,%3}, {%4,%5,%6,%7}, {%8,%9}, {%0,%1,%2,%3};"
                        : "+f"(acc[i][j][0]), "+f"(acc[i][j][1]),
                          "+f"(acc[i][j][2]), "+f"(acc[i][j][3])
                        : "r"(a[i][0]), "r"(a[i][1]), "r"(a[i][2]), "r"(a[i][3]),
                          "r"(b[j][0]), "r"(b[j][1]));
                }
        }
        if (kt + 1 < nk) {
            int nb = 1 - cur;
            As[nb][kseg+0][ar]=pa0.x; As[nb][kseg+1][ar]=pa0.y; As[nb][kseg+2][ar]=pa0.z; As[nb][kseg+3][ar]=pa0.w;
            As[nb][kseg+4][ar]=pa1.x; As[nb][kseg+5][ar]=pa1.y; As[nb][kseg+6][ar]=pa1.z; As[nb][kseg+7][ar]=pa1.w;
            Bs[nb][br][bc0+0]=pb0.x; Bs[nb][br][bc0+1]=pb0.y; Bs[nb][br][bc0+2]=pb0.z; Bs[nb][br][bc0+3]=pb0.w;
            Bs[nb][br][bc0+4]=pb1.x; Bs[nb][br][bc0+5]=pb1.y; Bs[nb][br][bc0+6]=pb1.z; Bs[nb][br][bc0+7]=pb1.w;
        }
        __syncthreads();
    }
    #pragma unroll
    for (int i = 0; i < 4; i++) {
        int r0 = rowBase + wm + i*16 + gq;
        #pragma unroll
        for (int j = 0; j < 4; j++) {
            int c0 = colBase + wn + j*8 + 2*tg;
            float v0 = fmaxf(acc[i][j][0] + ebias[c0],   0.f) + eres[(size_t)r0*N + c0];
            float v1 = fmaxf(acc[i][j][1] + ebias[c0+1], 0.f) + eres[(size_t)r0*N + c0 + 1];
            float v2 = fmaxf(acc[i][j][2] + ebias[c0],   0.f) + eres[(size_t)(r0+8)*N + c0];
            float v3 = fmaxf(acc[i][j][3] + ebias[c0+1], 0.f) + eres[(size_t)(r0+8)*N + c0 + 1];
            C[(size_t)r0*N + c0]         = v0;
            C[(size_t)r0*N + c0 + 1]     = v1;
            C[(size_t)(r0+8)*N + c0]     = v2;
            C[(size_t)(r0+8)*N + c0 + 1] = v3;
        }
    }
}

// ---------------------------------------------------------------------------
// TF32 tensor-core GEMM, N=64 (GCN1): C = A@B. M%128==0, K%16==0, N==64.
// ---------------------------------------------------------------------------
__global__ void __launch_bounds__(256)
k_gemm_tf32_64(const float* __restrict__ A, const float* __restrict__ B,
               float* __restrict__ C, int M, int K){
    __shared__ float As[2][16][132];
    __shared__ float Bs[2][16][68];
    int tid = threadIdx.x;
    int lane = tid & 31, warp = tid >> 5;
    int wm = (warp & 3) * 32;
    int wn = (warp >> 2) * 32;
    int rowBase = blockIdx.x*128;
    int ar = tid >> 1, kseg = (tid & 1) * 8;
    int br = tid >> 4, bc0 = (tid & 15) * 4;
    int gq = lane >> 2, tg = lane & 3;
    float acc[2][4][4];
    #pragma unroll
    for (int i=0;i<2;i++)
        #pragma unroll
        for (int j=0;j<4;j++)
            #pragma unroll
            for (int q=0;q<4;q++) acc[i][j][q]=0.f;

    int nk = K / 16;
    float4 pa0, pa1, pb0;
    {
        const float* Ar = A + (size_t)(rowBase+ar)*K + kseg;
        pa0 = *reinterpret_cast<const float4*>(Ar);
        pa1 = *reinterpret_cast<const float4*>(Ar + 4);
        pb0 = *reinterpret_cast<const float4*>(&B[(size_t)br*64 + bc0]);
    }
    As[0][kseg+0][ar]=pa0.x; As[0][kseg+1][ar]=pa0.y; As[0][kseg+2][ar]=pa0.z; As[0][kseg+3][ar]=pa0.w;
    As[0][kseg+4][ar]=pa1.x; As[0][kseg+5][ar]=pa1.y; As[0][kseg+6][ar]=pa1.z; As[0][kseg+7][ar]=pa1.w;
    Bs[0][br][bc0+0]=pb0.x; Bs[0][br][bc0+1]=pb0.y; Bs[0][br][bc0+2]=pb0.z; Bs[0][br][bc0+3]=pb0.w;
    __syncthreads();

    for (int kt = 0; kt < nk; kt++) {
        int cur = kt & 1;
        if (kt + 1 < nk) {
            int k0 = (kt+1)*16;
            const float* Ar = A + (size_t)(rowBase+ar)*K + k0 + kseg;
            pa0 = *reinterpret_cast<const float4*>(Ar);
            pa1 = *reinterpret_cast<const float4*>(Ar + 4);
            pb0 = *reinterpret_cast<const float4*>(&B[(size_t)(k0+br)*64 + bc0]);
        }
        #pragma unroll
        for (int k8 = 0; k8 < 16; k8 += 8) {
            unsigned a[2][4], b[4][2];
            #pragma unroll
            for (int i = 0; i < 2; i++) {
                int mr = wm + i*16 + gq;
                a[i][0] = f2tf32(As[cur][k8+tg][mr]);
                a[i][1] = f2tf32(As[cur][k8+tg][mr+8]);
                a[i][2] = f2tf32(As[cur][k8+4+tg][mr]);
                a[i][3] = f2tf32(As[cur][k8+4+tg][mr+8]);
            }
            #pragma unroll
            for (int j = 0; j < 4; j++) {
                int nc = wn + j*8 + gq;
                b[j][0] = f2tf32(Bs[cur][k8+tg][nc]);
                b[j][1] = f2tf32(Bs[cur][k8+4+tg][nc]);
            }
            #pragma unroll
            for (int i = 0; i < 2; i++)
                #pragma unroll
                for (int j = 0; j < 4; j++) {
                    asm volatile(
                        "mma.sync.aligned.m16n8k8.row.col.f32.tf32.tf32.f32 "
                        "{%0,%1,%2,%3}, {%4,%5,%6,%7}, {%8,%9}, {%0,%1,%2,%3};"
                        : "+f"(acc[i][j][0]), "+f"(acc[i][j][1]),
                          "+f"(acc[i][j][2]), "+f"(acc[i][j][3])
                        : "r"(a[i][0]), "r"(a[i][1]), "r"(a[i][2]), "r"(a[i][3]),
                          "r"(b[j][0]), "r"(b[j][1]));
                }
        }
        if (kt + 1 < nk) {
            int nb = 1 - cur;
            As[nb][kseg+0][ar]=pa0.x; As[nb][kseg+1][ar]=pa0.y; As[nb][kseg+2][ar]=pa0.z; As[nb][kseg+3][ar]=pa0.w;
            As[nb][kseg+4][ar]=pa1.x; As[nb][kseg+5][ar]=pa1.y; As[nb][kseg+6][ar]=pa1.z; As[nb][kseg+7][ar]=pa1.w;
            Bs[nb][br][bc0+0]=pb0.x; Bs[nb][br][bc0+1]=pb0.y; Bs[nb][br][bc0+2]=pb0.z; Bs[nb][br][bc0+3]=pb0.w;
        }
        __syncthreads();
    }
    #pragma unroll
    for (int i = 0; i < 2; i++) {
        int r0 = rowBase + wm + i*16 + gq;
        #pragma unroll
        for (int j = 0; j < 4; j++) {
            int c0 = wn + j*8 + 2*tg;
            C[(size_t)r0*64 + c0]         = acc[i][j][0];
            C[(size_t)r0*64 + c0 + 1]     = acc[i][j][1];
            C[(size_t)(r0+8)*64 + c0]     = acc[i][j][2];
            C[(size_t)(r0+8)*64 + c0 + 1] = acc[i][j][3];
        }
    }
}

// ---------------------------------------------------------------------------
// TopK: single-block radix select (unchanged, proven)
// ---------------------------------------------------------------------------
__device__ __forceinline__ unsigned fkey(float f){
    unsigned u = __float_as_uint(f);
    return (u & 0x80000000u) ? ~u : (u | 0x80000000u);
}

// n must be a multiple of 4
__global__ void k_select(const float* __restrict__ score, int n, int K,
                         int* __restrict__ keep, int* __restrict__ nid, int* ezero){
    __shared__ unsigned hist[256];
    __shared__ int warpsum[32];
    __shared__ unsigned sh_prefix; __shared__ int sh_krem;
    __shared__ int sh_run;
    int tid = threadIdx.x;                     // 1024 threads
    if (tid == 0) { sh_prefix = 0u; sh_krem = K; if (ezero) *ezero = 0; }
    __syncthreads();
    for (int pass = 0; pass < 4; pass++) {
        if (tid < 256) hist[tid] = 0u;
        __syncthreads();
        int shift = 24 - 8*pass;
        unsigned pfx = sh_prefix;
        unsigned hm = (pass > 0) ? (0xFFFFFFFFu << (shift+8)) : 0u;
        for (int b = tid*4; b < n; b += 4096) {
            float4 v = *reinterpret_cast<const float4*>(score + b);
            unsigned k0 = fkey(v.x), k1 = fkey(v.y), k2 = fkey(v.z), k3 = fkey(v.w);
            if ((k0 & hm) == (pfx & hm)) atomicAdd(&hist[(k0 >> shift) & 0xFFu], 1u);
            if ((k1 & hm) == (pfx & hm)) atomicAdd(&hist[(k1 >> shift) & 0xFFu], 1u);
            if ((k2 & hm) == (pfx & hm)) atomicAdd(&hist[(k2 >> shift) & 0xFFu], 1u);
            if ((k3 & hm) == (pfx & hm)) atomicAdd(&hist[(k3 >> shift) & 0xFFu], 1u);
        }
        __syncthreads();
        if (tid == 0) {
            unsigned k = (unsigned)sh_krem, cum = 0; int b = 0;
            for (int i = 255; i >= 0; i--) {
                unsigned c = hist[i];
                if (cum + c >= k) { b = i; break; }
                cum += c;
            }
            sh_prefix = pfx | ((unsigned)b << shift);
            sh_krem = (int)(k - cum);
        }
        __syncthreads();
    }
    unsigned prefix = sh_prefix; int krem = sh_krem;
    if (tid == 0) sh_run = 0;
    __syncthreads();
    for (int base = 0; base < n; base += 4096) {
        int i0 = base + tid*4;
        int pk[4]; int s = 0;
        unsigned kk[4];
        if (i0 < n) {
            float4 v = *reinterpret_cast<const float4*>(score + i0);
            kk[0] = fkey(v.x); kk[1] = fkey(v.y); kk[2] = fkey(v.z); kk[3] = fkey(v.w);
            #pragma unroll
            for (int j = 0; j < 4; j++) {
                int g = (kk[j] > prefix) ? 1 : 0;
                int t = (kk[j] == prefix) ? 1 : 0;
                pk[j] = (g << 16) | t;
                s += pk[j];
            }
        } else { pk[0]=pk[1]=pk[2]=pk[3]=0; }
        int tot;
        int incl = blk_scan_incl(s, tid, warpsum, &tot);
        int run = sh_run + incl - s;
        if (i0 < n) {
            #pragma unroll
            for (int j = 0; j < 4; j++) {
                int g_before = run >> 16, t_before = run & 0xFFFF;
                int g = pk[j] >> 16, t = pk[j] & 0xFFFF;
                int kp = g | (t && (t_before < krem));
                keep[i0+j] = kp;
                nid[i0+j]  = g_before + (t_before < krem ? t_before : krem);
                run += pk[j];
            }
        }
        __syncthreads();
        if (tid == 0) sh_run += tot;
        __syncthreads();
    }
}

__global__ void k_pool_gather(const float* __restrict__ h, const float* __restrict__ score,
                              const int* __restrict__ keep, const int* __restrict__ nid,
                              float* __restrict__ out, int n, int F){
    int i = blockIdx.x*blockDim.x + threadIdx.x;
    if (i >= n*F) return;
    int node = i / F, c = i % F;
    if (keep[node]) out[(size_t)nid[node]*F + c] = h[i] * score[node];
}

__global__ void k_ecompact(const int* __restrict__ src, const int* __restrict__ dst,
                           const int* __restrict__ keep, const int* __restrict__ nid,
                           const int* pE, int Emax, int* __restrict__ ns,
                           int* __restrict__ nd, int* cntOut, int* deg){
    int e = blockIdx.x*blockDim.x + threadIdx.x;
    if (e >= Emax) return;
    int E = pE ? *pE : Emax;
    if (e >= E) return;
    int s = src[e], d = dst[e];
    if (keep[s] && keep[d]) {
        int j = atomicAdd(cntOut, 1);
        int nsd = nid[s], ndd = nid[d];
        ns[j] = nsd; nd[j] = ndd;
        atomicAdd(&deg[ndd], 1);
    }
}

// ---------------------------------------------------------------------------
// GAT
// ---------------------------------------------------------------------------
__device__ __forceinline__ float lrelu(float x){ return x > 0.f ? x : 0.2f*x; }

__global__ void k_gat_va(const float* __restrict__ gw, const float* __restrict__ as,
                         const float* __restrict__ ad, float* __restrict__ va){
    int t = blockIdx.x*blockDim.x + threadIdx.x;
    int w = t >> 5, lane = t & 31;
    if (w >= FIN*16) return;
    int k = w >> 4, col = w & 15;
    int h = col & 7;
    const float* avec = ((col < 8) ? as : ad) + h*H2c;
    const float* grow = gw + (size_t)k*(HEADSc*H2c) + h*H2c;
    float s = 0;
    for (int c = lane; c < H2c; c += 32) s += grow[c]*avec[c];
    #pragma unroll
    for (int o = 16; o; o >>= 1) s += __shfl_down_sync(0xFFFFFFFFu, s, o);
    if (!lane) va[k*16 + col] = s;
}

// reshape: wt[h*128+k, c] = gw[k, h*128+c]  (wt is 1024 x 128)
__global__ void k_build_wt(const float* __restrict__ gw, float* __restrict__ wt){
    int t = blockIdx.x*blockDim.x + threadIdx.x;
    if (t >= HEADSc*H2c*H2c) return;
    int i = t >> 7, c = t & 127;
    int h = i >> 7, k = i & 127;
    wt[t] = gw[(size_t)k*(HEADSc*H2c) + h*H2c + c];
}

__global__ void k_gat_att(const int* __restrict__ rowptr, const int* __restrict__ csr,
                          const float* __restrict__ alad, float* __restrict__ att,
                          float* __restrict__ attself, int n){
    int t = blockIdx.x*blockDim.x + threadIdx.x;
    int node = t >> 3, h = t & 7;
    if (node >= n) return;
    int e0 = rowptr[node], e1 = rowptr[node+1];
    float add = alad[node*16 + 8 + h];
    float selfv = lrelu(alad[node*16 + h] + add);
    float m = selfv;
    for (int p = e0; p < e1; p++) {
        int s = csr[p];
        m = fmaxf(m, lrelu(alad[s*16 + h] + add));
    }
    float dn = expf(selfv - m);
    for (int p = e0; p < e1; p++) {
        int s = csr[p];
        float ex = expf(lrelu(alad[s*16 + h] + add) - m);
        att[p*8 + h] = ex;
        dn += ex;
    }
    float inv = 0.125f / dn;
    for (int p = e0; p < e1; p++) att[p*8 + h] *= inv;
    attself[node*8 + h] = expf(selfv - m) * inv;
}

// warp per node: z[d, h*128 + f] = attself_h*hp2[d,f] + sum_e att_h*hp2[s,f]
__global__ void k_gat_gather_z(const int* __restrict__ rowptr, const int* __restrict__ csr,
                               const float* __restrict__ hp2, const float* __restrict__ att,
                               const float* __restrict__ attself,
                               float* __restrict__ Z, int n){
    int t = blockIdx.x*blockDim.x + threadIdx.x;
    int w = t >> 5, lane = t & 31;
    if (w >= n) return;
    int e0 = rowptr[w], e1 = rowptr[w+1];
    float z[32];
    #pragma unroll
    for (int j = 0; j < 32; j++) z[j] = 0.f;
    {
        float av = (lane < 8) ? attself[w*8 + lane] : 0.f;
        const float* hr = hp2 + (size_t)w*H2c;
        float x0 = hr[lane], x1 = hr[lane+32], x2 = hr[lane+64], x3 = hr[lane+96];
        #pragma unroll
        for (int h = 0; h < HEADSc; h++) {
            float a = __shfl_sync(0xFFFFFFFFu, av, h);
            z[h*4+0] += a*x0; z[h*4+1] += a*x1; z[h*4+2] += a*x2; z[h*4+3] += a*x3;
        }
    }
    for (int p = e0; p < e1; p++) {
        float av = (lane < 8) ? att[p*8 + lane] : 0.f;
        const float* hr = hp2 + (size_t)csr[p]*H2c;
        float x0 = hr[lane], x1 = hr[lane+32], x2 = hr[lane+64], x3 = hr[lane+96];
        #pragma unroll
        for (int h = 0; h < HEADSc; h++) {
            float a = __shfl_sync(0xFFFFFFFFu, av, h);
            z[h*4+0] += a*x0; z[h*4+1] += a*x1; z[h*4+2] += a*x2; z[h*4+3] += a*x3;
        }
    }
    float* zr = Z + (size_t)w*(HEADSc*H2c);
    #pragma unroll
    for (int h = 0; h < HEADSc; h++) {
        zr[h*H2c + lane]      = z[h*4+0];
        zr[h*H2c + lane + 32] = z[h*4+1];
        zr[h*H2c + lane + 64] = z[h*4+2];
        zr[h*H2c + lane + 96] = z[h*4+3];
    }
}

// ---------------------------------------------------------------------------
// GCN1 gather
// ---------------------------------------------------------------------------
__global__ void k_gcn_gather(const int* __restrict__ rowptr, const int* __restrict__ csr,
                             const float* __restrict__ y, const float* __restrict__ dinv,
                             const float* __restrict__ b, float* __restrict__ o,
                             int n, int C, int relu){
    int t = blockIdx.x*blockDim.x + threadIdx.x;
    int w = t >> 5, lane = t & 31;
    if (w >= n) return;
    int e0 = rowptr[w], e1 = rowptr[w+1];
    float dd = dinv[w];
    float a0 = 0.f, a1 = 0.f;
    bool has2 = (lane + 32) < C;
    for (int p = e0; p < e1; p++) {
        int s = csr[p];
        float ds = dinv[s];
        a0 += ds * y[(size_t)s*C + lane];
        if (has2) a1 += ds * y[(size_t)s*C + lane + 32];
    }
    float v0 = dd*a0 + dd*dd*y[(size_t)w*C + lane] + b[lane];
    o[(size_t)w*C + lane] = relu ? fmaxf(v0, 0.f) : v0;
    if (has2) {
        float v1 = dd*a1 + dd*dd*y[(size_t)w*C + lane + 32] + b[lane+32];
        o[(size_t)w*C + lane + 32] = relu ? fmaxf(v1, 0.f) : v1;
    }
}

// ---------------------------------------------------------------------------
// Collapsed GCN2 + global mean + log_softmax
// ---------------------------------------------------------------------------
__global__ void k_wsum_init(const float* __restrict__ dinv, float* __restrict__ acc,
                            float* __restrict__ r, int n){
    int i = blockIdx.x*blockDim.x + threadIdx.x;
    if (i < n) acc[i] = dinv[i];
    if (i < H1c) r[i] = 0.f;
}
__global__ void k_wsum_edge(const int* __restrict__ src, const int* __restrict__ dst,
                            const float* __restrict__ dinv, float* __restrict__ acc,
                            const int* pE, int Emax){
    int e = blockIdx.x*blockDim.x + threadIdx.x;
    if (e >= Emax) return;
    if (e >= *pE) return;
    atomicAdd(&acc[src[e]], dinv[dst[e]]);
}
__global__ void k_wcolsum(const float* __restrict__ o1, const float* __restrict__ dinv,
                          const float* __restrict__ acc, float* __restrict__ r, int n){
    __shared__ float sh[H1c];
    int tid = threadIdx.x;                 // 256 threads
    if (tid < H1c) sh[tid] = 0.f;
    __syncthreads();
    int lane = tid & 31;
    int gw = (blockIdx.x*256 + tid) >> 5;
    int nw = (gridDim.x*256) >> 5;
    float a0 = 0.f, a1 = 0.f;
    for (int row = gw; row < n; row += nw) {
        float wv = dinv[row]*acc[row];
        a0 += wv * o1[(size_t)row*H1c + lane];
        a1 += wv * o1[(size_t)row*H1c + lane + 32];
    }
    atomicAdd(&sh[lane], a0);
    atomicAdd(&sh[lane + 32], a1);
    __syncthreads();
    if (tid < H1c) atomicAdd(&r[tid], sh[tid]);
}
__global__ void k_final(const float* __restrict__ r, const float* __restrict__ g2w,
                        const float* __restrict__ b, float* __restrict__ out){
    __shared__ float gv[NCc];
    int tid = threadIdx.x;                 // 64 threads
    if (tid < NCc) {
        float s = 0.f;
        for (int f = 0; f < H1c; f++) s += r[f]*g2w[f*NCc + tid];
        gv[tid] = s / (float)K2c + b[tid];
    }
    __syncthreads();
    if (tid == 0) {
        float mxv = -1e30f;
        for (int c = 0; c < NCc; c++) mxv = fmaxf(mxv, gv[c]);
        float s = 0;
        for (int c = 0; c < NCc; c++) s += expf(gv[c] - mxv);
        float l = logf(s);
        for (int c = 0; c < NCc; c++) out[c] = gv[c] - mxv - l;
    }
}

// ---------------------------------------------------------------------------
// Host side
// ---------------------------------------------------------------------------
static void gemm_launch_s(cudaStream_t st, const float* A, const float* B,
                          const float* B2, const float* B3, float* C,
                          int M, int N, int K, int Nh,
                          const float* ebias = nullptr, const float* eres = nullptr,
                          int erelu = 0){
    dim3 grid(CDIV(N, GBN), CDIV(M, GBM));
    k_gemm<<<grid, 256, 0, st>>>(A, B, B2, B3, C, M, N, K, Nh, ebias, eres, erelu);
}

extern "C" void kernel_launch(void* const* d_in, const int* in_sizes, int n_in,
                              void* d_out, int out_size){
    const float* x    = (const float*)d_in[0];
    const int*   ei   = (const int*)  d_in[1];
    const float* s1wl = (const float*)d_in[3];
    const float* s1bl = (const float*)d_in[4];
    const float* s1wr = (const float*)d_in[5];
    const float* r1w  = (const float*)d_in[6];
    const float* r1b  = (const float*)d_in[7];
    const float* p1w  = (const float*)d_in[8];
    const float* s2wl = (const float*)d_in[9];
    const float* s2bl = (const float*)d_in[10];
    const float* s2wr = (const float*)d_in[11];
    const float* r2w  = (const float*)d_in[12];
    const float* r2b  = (const float*)d_in[13];
    const float* p2w  = (const float*)d_in[14];
    const float* gw   = (const float*)d_in[15];
    const float* gas  = (const float*)d_in[16];
    const float* gad  = (const float*)d_in[17];
    const float* gb   = (const float*)d_in[18];
    const float* g1w  = (const float*)d_in[19];
    const float* g1b  = (const float*)d_in[20];
    const float* g2w  = (const float*)d_in[21];
    const float* g2b  = (const float*)d_in[22];
    float* out = (float*)d_out;

    const int* src0 = ei;
    const int* dst0 = ei + Ee;

    float *aggr, *gP, *gQR, *h1, *hp1, *h2, *hp2, *Z, *wt, *va, *alad, *att, *attself;
    float *gin, *y1, *o1, *accv, *rvec, *dinv, *score;
    int *cnt, *rowptr, *wp, *csr, *keep, *nid, *src1, *dst1, *src2, *dst2, *Ecnt;
    cudaGetSymbolAddress((void**)&aggr,    d_aggr);
    cudaGetSymbolAddress((void**)&cnt,     d_cnt);
    cudaGetSymbolAddress((void**)&rowptr,  d_rowptr);
    cudaGetSymbolAddress((void**)&wp,      d_wp);
    cudaGetSymbolAddress((void**)&csr,     d_csr);
    cudaGetSymbolAddress((void**)&gP,      d_gP);
    cudaGetSymbolAddress((void**)&gQR,     d_gQR);
    cudaGetSymbolAddress((void**)&h1,      d_h1);
    cudaGetSymbolAddress((void**)&hp1,     d_hp1);
    cudaGetSymbolAddress((void**)&h2,      d_h2);
    cudaGetSymbolAddress((void**)&hp2,     d_hp2);
    cudaGetSymbolAddress((void**)&Z,       d_z);
    cudaGetSymbolAddress((void**)&wt,      d_wt);
    cudaGetSymbolAddress((void**)&va,      d_va);
    cudaGetSymbolAddress((void**)&alad,    d_alad);
    cudaGetSymbolAddress((void**)&att,     d_att);
    cudaGetSymbolAddress((void**)&attself, d_attself);
    cudaGetSymbolAddress((void**)&gin,     d_gin);
    cudaGetSymbolAddress((void**)&y1,      d_y1);
    cudaGetSymbolAddress((void**)&o1,      d_o1);
    cudaGetSymbolAddress((void**)&accv,    d_acc);
    cudaGetSymbolAddress((void**)&rvec,    d_rvec);
    cudaGetSymbolAddress((void**)&dinv,    d_dinv);
    cudaGetSymbolAddress((void**)&score,   d_score);
    cudaGetSymbolAddress((void**)&keep,    d_keep);
    cudaGetSymbolAddress((void**)&nid,     d_nid);
    cudaGetSymbolAddress((void**)&src1,    d_src1);
    cudaGetSymbolAddress((void**)&dst1,    d_dst1);
    cudaGetSymbolAddress((void**)&src2,    d_src2);
    cudaGetSymbolAddress((void**)&dst2,    d_dst2);
    cudaGetSymbolAddress((void**)&Ecnt,    d_Ecnt);

    static cudaStream_t s1 = nullptr, s2 = nullptr;
    static cudaEvent_t  ev[10];
    if (!s1) {
        cudaStreamCreate(&s1);
        cudaStreamCreate(&s2);
        for (int i = 0; i < 10; i++) cudaEventCreateWithFlags(&ev[i], cudaEventDisableTiming);
    }
    cudaStream_t M = 0;

    const int ET_GRID = CDIV(Ee, 256);

    // ===== Phase A: SAGE1 GEMM (M) || CSR1 (s1) || weight prep (s2) =====
    cudaEventRecord(ev[0], M);
    cudaStreamWaitEvent(s1, ev[0], 0);
    cudaStreamWaitEvent(s2, ev[0], 0);
    gemm_launch_s(M, x, s1wl, s1wr, r1w, gQR, Nn, 3*H1c, FIN, H1c);  // Y=x@[wl|wr|res]
    k_gat_va<<<CDIV(FIN*16*32, 256), 256, 0, s2>>>(gw, gas, gad, va);
    k_build_wt<<<CDIV(HEADSc*H2c*H2c, 256), 256, 0, s2>>>(gw, wt);
    cudaEventRecord(ev[8], s2);                      // va + wt ready
    k_count<<<ET_GRID, 256, 0, s1>>>(dst0, cnt, nullptr, Ee);
    k_exscan<<<1, 1024, 0, s1>>>(cnt, rowptr, wp, Nn, nullptr);
    k_fill<<<ET_GRID, 256, 0, s1>>>(src0, dst0, wp, csr, nullptr, Ee);
    cudaEventRecord(ev[1], s1);
    cudaStreamWaitEvent(M, ev[1], 0);

    // ===== SAGE1 gather (fused score) + Pool 1 (M) =====
    k_sage1_gather<<<CDIV(Nn*32, 256), 256, 0, M>>>(rowptr, csr, gQR, s1bl, r1b, p1w,
                                                    h1, score, Nn);
    k_select<<<1, 1024, 0, M>>>(score, Nn, K1c, keep, nid, Ecnt);

    // ===== Phase C: pool_gather1 (M)  ||  CSR2 chain (s1) =====
    cudaEventRecord(ev[2], M);
    cudaStreamWaitEvent(s1, ev[2], 0);
    k_pool_gather<<<CDIV(Nn*H1c, 256), 256, 0, M>>>(h1, score, keep, nid, hp1, Nn, H1c);
    cudaEventRecord(ev[3], M);                       // hp1 ready
    k_ecompact<<<ET_GRID, 256, 0, s1>>>(src0, dst0, keep, nid, nullptr, Ee,
                                        src1, dst1, Ecnt, cnt);
    k_exscan<<<1, 1024, 0, s1>>>(cnt, rowptr, wp, K1c, nullptr);
    k_fill<<<ET_GRID, 256, 0, s1>>>(src1, dst1, wp, csr, Ecnt, Ee);

    // ===== Phase D: QR GEMM (M)  ||  mean_gather + P GEMM (s1) =====
    cudaStreamWaitEvent(s1, ev[3], 0);
    k_mean_gather<<<CDIV(K1c*32, 256), 256, 0, s1>>>(rowptr, csr, hp1, aggr, K1c);
    gemm_launch_s(s1, aggr, s2wl, nullptr, nullptr, gP, K1c, H2c, H1c, 0);
    gemm_launch_s(M, hp1, s2wr, r2w, nullptr, gQR, K1c, 2*H2c, H1c, H2c);
    cudaEventRecord(ev[4], s1);
    cudaStreamWaitEvent(M, ev[4], 0);

    // ===== SAGE2 combine (fused score) + Pool 2 (M) =====
    k_sage2_combine<<<CDIV(K1c*32, 256), 256, 0, M>>>(gP, gQR, s2bl, r2b, p2w,
                                                      h2, score, K1c);
    k_select<<<1, 1024, 0, M>>>(score, K1c, K2c, keep, nid, Ecnt + 1);

    // ===== Phase F: pool2 + alad (M) || CSR3 (s1) || wsum (s2) =====
    cudaEventRecord(ev[5], M);
    cudaStreamWaitEvent(s1, ev[5], 0);
    k_pool_gather<<<CDIV(K1c*H2c, 256), 256, 0, M>>>(h2, score, keep, nid, hp2, K1c, H2c);
    cudaStreamWaitEvent(M, ev[8], 0);                // va ready
    gemm_launch_s(M, hp2, va, nullptr, nullptr, alad, K2c, 16, H2c, 0);
    k_ecompact<<<ET_GRID, 256, 0, s1>>>(src1, dst1, keep, nid, Ecnt, Ee,
                                        src2, dst2, Ecnt + 1, cnt);
    k_exscan<<<1, 1024, 0, s1>>>(cnt, rowptr, wp, K2c, dinv);
    cudaEventRecord(ev[6], s1);                      // dinv + counts ready
    k_fill<<<ET_GRID, 256, 0, s1>>>(src2, dst2, wp, csr, Ecnt + 1, Ee);
    cudaEventRecord(ev[9], s1);                      // CSR3 ready
    cudaStreamWaitEvent(s2, ev[6], 0);               // wsum on s2, parallel to fill3
    k_wsum_init<<<CDIV(K2c, 256), 256, 0, s2>>>(dinv, accv, rvec, K2c);
    k_wsum_edge<<<ET_GRID, 256, 0, s2>>>(src2, dst2, dinv, accv, Ecnt + 1, Ee);
    cudaEventRecord(ev[7], s2);                      // wsum ready
    cudaStreamWaitEvent(M, ev[9], 0);

    // ===== GAT (aggregate-then-project, tf32) + GCN1 (tf32) + head (M) =====
    k_gat_att<<<CDIV(K2c*8, 256), 256, 0, M>>>(rowptr, csr, alad, att, attself, K2c);
    k_gat_gather_z<<<CDIV(K2c*32, 256), 256, 0, M>>>(rowptr, csr, hp2, att, attself, Z, K2c);
    {   // gin = relu(Z@wt + gb) + hp2, tf32 tensor cores (12800x128x1024)
        dim3 g(1, K2c/128);
        k_gemm_tf32<<<g, 256, 0, M>>>(Z, wt, gin, K2c, H2c, HEADSc*H2c, gb, hp2);
    }

    k_gemm_tf32_64<<<K2c/128, 256, 0, M>>>(gin, g1w, y1, K2c, H2c);   // y1 = gin@g1w
    k_gcn_gather<<<CDIV(K2c*32, 256), 256, 0, M>>>(rowptr, csr, y1, dinv, g1b, o1, K2c, H1c, 1);

    cudaStreamWaitEvent(M, ev[7], 0);
    k_wcolsum<<<64, 256, 0, M>>>(o1, dinv, accv, rvec, K2c);
    k_final<<<1, 64, 0, M>>>(rvec, g2w, g2b, out);
}

// round 17
// speedup vs baseline: 1.0295x; 1.0295x over previous
#include <cuda_runtime.h>
#include <math.h>
#include <stdint.h>

#define Nn    20000
#define Ee    320000
#define FIN   128
#define H1c   64
#define H2c   128
#define HEADSc 8
#define NCc   40
#define K1c   16000
#define K2c   12800

#define CDIV(a,b) (((a)+(b)-1)/(b))

// ---------------------------------------------------------------------------
// Device scratch
// ---------------------------------------------------------------------------
__device__ float d_aggr[K1c*H1c];
__device__ int   d_cnt[Nn];
__device__ int   d_rowptr[Nn+1];
__device__ int   d_wp[Nn];
__device__ int   d_csr[Ee];
__device__ float d_gP[Nn*H2c];
__device__ float d_gQR[Nn*3*H1c > Nn*2*H2c ? Nn*3*H1c : Nn*2*H2c];
__device__ float d_h1[Nn*H1c];
__device__ float d_hp1[K1c*H1c];
__device__ float d_h2[K1c*H2c];
__device__ float d_hp2[K2c*H2c];
__device__ float d_z[K2c*HEADSc*H2c];      // 12800 x 1024 aggregated hp2-space
__device__ float d_wt[HEADSc*H2c*H2c];     // 1024 x 128 reshaped gat weight
__device__ float d_va[FIN*16];
__device__ float d_alad[K2c*16];
__device__ float d_att[Ee*HEADSc];
__device__ float d_attself[K2c*HEADSc];
__device__ float d_gin[K2c*H2c];
__device__ float d_y1[K2c*H1c];
__device__ float d_o1[K2c*H1c];
__device__ float d_acc[K2c];               // out-edge dinv sums
__device__ float d_rvec[H1c];              // wsum^T @ o1
__device__ float d_dinv[K2c];
__device__ float d_score[Nn];
__device__ int   d_keep[Nn];
__device__ int   d_nid[Nn];
__device__ int   d_src1[Ee], d_dst1[Ee], d_src2[Ee], d_dst2[Ee];
__device__ int   d_Ecnt[2];

// ---------------------------------------------------------------------------
// CSR build
// ---------------------------------------------------------------------------
__global__ void k_count(const int* __restrict__ dst, int* __restrict__ cnt,
                        const int* pE, int Emax){
    int e = blockIdx.x*blockDim.x + threadIdx.x;
    if (e >= Emax) return;
    int E = pE ? *pE : Emax;
    if (e < E) atomicAdd(&cnt[dst[e]], 1);
}

__device__ __forceinline__ int blk_scan_incl(int v, int tid, int* warpsum, int* total){
    __syncthreads();
    int lane = tid & 31, wid = tid >> 5;
    #pragma unroll
    for (int o = 1; o < 32; o <<= 1) {
        int t = __shfl_up_sync(0xFFFFFFFFu, v, o);
        if (lane >= o) v += t;
    }
    if (lane == 31) warpsum[wid] = v;
    __syncthreads();
    if (wid == 0) {
        int s = warpsum[lane];
        #pragma unroll
        for (int o = 1; o < 32; o <<= 1) {
            int t = __shfl_up_sync(0xFFFFFFFFu, s, o);
            if (lane >= o) s += t;
        }
        warpsum[lane] = s;
    }
    __syncthreads();
    *total = warpsum[31];
    return v + (wid ? warpsum[wid-1] : 0);
}

// single-block exclusive scan, 4 ints/thread/iter. Zeroes deg[0..nzero) after
// reading; optionally emits dinv[i] = rsqrt(deg[i]+1). n, nzero % 4 == 0.
__global__ void k_exscan(int* __restrict__ deg, int* __restrict__ rowptr,
                         int* __restrict__ wp, int n, int nzero,
                         float* __restrict__ dinvOut){
    __shared__ int warpsum[32];
    __shared__ int sh_run;
    int tid = threadIdx.x;                  // 1024 threads
    if (tid == 0) sh_run = 0;
    __syncthreads();
    int ntot = (n > nzero) ? n : nzero;
    for (int base = 0; base < ntot; base += 4096) {
        int i0 = base + tid*4;
        int4 v = make_int4(0,0,0,0);
        if (i0 < n) v = *reinterpret_cast<const int4*>(deg + i0);
        int s = v.x + v.y + v.z + v.w;
        int tot;
        int incl = blk_scan_incl(s, tid, warpsum, &tot);
        int run = sh_run + incl - s;
        if (i0 < n) {
            rowptr[i0]   = run; wp[i0]   = run; run += v.x;
            rowptr[i0+1] = run; wp[i0+1] = run; run += v.y;
            rowptr[i0+2] = run; wp[i0+2] = run; run += v.z;
            rowptr[i0+3] = run; wp[i0+3] = run;
            if (dinvOut) {
                dinvOut[i0]   = rsqrtf((float)(v.x + 1));
                dinvOut[i0+1] = rsqrtf((float)(v.y + 1));
                dinvOut[i0+2] = rsqrtf((float)(v.z + 1));
                dinvOut[i0+3] = rsqrtf((float)(v.w + 1));
            }
        }
        if (i0 < nzero) *reinterpret_cast<int4*>(deg + i0) = make_int4(0,0,0,0);
        __syncthreads();
        if (tid == 0) sh_run += tot;
        __syncthreads();
    }
    if (tid == 0) rowptr[n] = sh_run;
}

__global__ void k_fill(const int* __restrict__ src, const int* __restrict__ dst,
                       int* __restrict__ wp, int* __restrict__ csr,
                       const int* pE, int Emax){
    int e = blockIdx.x*blockDim.x + threadIdx.x;
    if (e >= Emax) return;
    int E = pE ? *pE : Emax;
    if (e >= E) return;
    int d = dst[e];
    int p = atomicAdd(&wp[d], 1);
    csr[p] = src[e];
}

// ---------------------------------------------------------------------------
// SAGE gathers
// ---------------------------------------------------------------------------
__global__ void k_sage1_gather(const int* __restrict__ rowptr, const int* __restrict__ csr,
                               const float* __restrict__ Y,
                               const float* __restrict__ bl, const float* __restrict__ rb,
                               float* __restrict__ h, int n){
    int t = blockIdx.x*blockDim.x + threadIdx.x;
    int w = t >> 5, lane = t & 31;
    if (w >= n) return;
    int e0 = rowptr[w], e1 = rowptr[w+1];
    float a0 = 0.f, a1 = 0.f;
    for (int p = e0; p < e1; p++) {
        const float* yr = Y + (size_t)csr[p]*192;
        a0 += yr[lane];
        a1 += yr[32 + lane];
    }
    float inv = 1.f / fmaxf((float)(e1 - e0), 1.f);
    a0 *= inv; a1 *= inv;
    const float* yw = Y + (size_t)w*192;
    h[w*H1c + lane]      = fmaxf(a0 + yw[64+lane] + bl[lane],    0.f) + yw[128+lane] + rb[lane];
    h[w*H1c + 32 + lane] = fmaxf(a1 + yw[96+lane] + bl[32+lane], 0.f) + yw[160+lane] + rb[32+lane];
}

__global__ void k_mean_gather(const int* __restrict__ rowptr, const int* __restrict__ csr,
                              const float* __restrict__ x, float* __restrict__ out, int n){
    int t = blockIdx.x*blockDim.x + threadIdx.x;
    int w = t >> 5, lane = t & 31;
    if (w >= n) return;
    int e0 = rowptr[w], e1 = rowptr[w+1];
    float a0 = 0.f, a1 = 0.f;
    for (int p = e0; p < e1; p++) {
        int s = csr[p];
        a0 += x[s*H1c + lane];
        a1 += x[s*H1c + 32 + lane];
    }
    float inv = 1.f / fmaxf((float)(e1 - e0), 1.f);
    out[w*H1c + lane]      = a0 * inv;
    out[w*H1c + 32 + lane] = a1 * inv;
}

__global__ void k_sage_combine(const float* __restrict__ P, const float* __restrict__ QR,
                               const float* __restrict__ bl, const float* __restrict__ rb,
                               float* __restrict__ h, int n, int C){
    int i = blockIdx.x*blockDim.x + threadIdx.x;
    if (i >= n*C) return;
    int node = i / C, c = i % C;
    const float* qr = QR + (size_t)node*2*C;
    float v = P[i] + qr[c] + bl[c];
    h[i] = fmaxf(v, 0.f) + qr[C + c] + rb[c];
}

// ---------------------------------------------------------------------------
// SGEMM (fp32): C = A@B, 128x128 tile, BK=16, double-buffered, 8x8/thread.
// ---------------------------------------------------------------------------
#define GBM 128
#define GBN 128
#define GBK 16
__device__ __forceinline__ float bsel_load(const float* __restrict__ B,
                                           const float* __restrict__ B2,
                                           const float* __restrict__ B3,
                                           int gk, int gc, int N, int Nh){
    if (gc >= N) return 0.f;
    if (!B2) return B[(size_t)gk*N + gc];
    if (gc < Nh) return B[(size_t)gk*Nh + gc];
    if (!B3 || gc < 2*Nh) return B2[(size_t)gk*Nh + gc - Nh];
    return B3[(size_t)gk*Nh + gc - 2*Nh];
}

__global__ void __launch_bounds__(256)
k_gemm(const float* __restrict__ A, const float* __restrict__ B,
       const float* __restrict__ B2, const float* __restrict__ B3,
       float* __restrict__ C, int M, int N, int K, int Nh,
       const float* __restrict__ ebias, const float* __restrict__ eres, int erelu){
    __shared__ float As[2][GBK][GBM+4];
    __shared__ float Bs[2][GBK][GBN];
    int tid = threadIdx.x;                    // 256 threads
    int rowBase = blockIdx.y*GBM, colBase = blockIdx.x*GBN;
    int tr = tid >> 4, tc = tid & 15;
    int ar = tid >> 1, kseg = (tid & 1) * 8;
    int br = tid >> 4, bc0 = (tid & 15) * 8;
    float acc[8][8];
    #pragma unroll
    for (int i = 0; i < 8; i++)
        #pragma unroll
        for (int j = 0; j < 8; j++) acc[i][j] = 0.f;

    int nk = K / GBK;
    float4 pa0, pa1; float pb[8];
    {
        int gr = rowBase + ar;
        pa0 = make_float4(0.f,0.f,0.f,0.f); pa1 = pa0;
        if (gr < M) {
            pa0 = *reinterpret_cast<const float4*>(&A[(size_t)gr*K + kseg]);
            pa1 = *reinterpret_cast<const float4*>(&A[(size_t)gr*K + kseg + 4]);
        }
        #pragma unroll
        for (int j = 0; j < 8; j++)
            pb[j] = bsel_load(B, B2, B3, br, colBase + bc0 + j, N, Nh);
    }
    As[0][kseg+0][ar]=pa0.x; As[0][kseg+1][ar]=pa0.y; As[0][kseg+2][ar]=pa0.z; As[0][kseg+3][ar]=pa0.w;
    As[0][kseg+4][ar]=pa1.x; As[0][kseg+5][ar]=pa1.y; As[0][kseg+6][ar]=pa1.z; As[0][kseg+7][ar]=pa1.w;
    #pragma unroll
    for (int j = 0; j < 8; j++) Bs[0][br][bc0+j] = pb[j];
    __syncthreads();

    for (int kt = 0; kt < nk; kt++) {
        int cur = kt & 1;
        if (kt + 1 < nk) {
            int k0 = (kt+1)*GBK;
            int gr = rowBase + ar;
            pa0 = make_float4(0.f,0.f,0.f,0.f); pa1 = pa0;
            if (gr < M) {
                pa0 = *reinterpret_cast<const float4*>(&A[(size_t)gr*K + k0 + kseg]);
                pa1 = *reinterpret_cast<const float4*>(&A[(size_t)gr*K + k0 + kseg + 4]);
            }
            #pragma unroll
            for (int j = 0; j < 8; j++)
                pb[j] = bsel_load(B, B2, B3, k0 + br, colBase + bc0 + j, N, Nh);
        }
        #pragma unroll
        for (int kk = 0; kk < GBK; kk++) {
            float a[8], b[8];
            #pragma unroll
            for (int i = 0; i < 4; i++) { a[i] = As[cur][kk][tr*4+i]; a[4+i] = As[cur][kk][64+tr*4+i]; }
            #pragma unroll
            for (int j = 0; j < 4; j++) { b[j] = Bs[cur][kk][tc*4+j]; b[4+j] = Bs[cur][kk][64+tc*4+j]; }
            #pragma unroll
            for (int i = 0; i < 8; i++)
                #pragma unroll
                for (int j = 0; j < 8; j++) acc[i][j] += a[i]*b[j];
        }
        if (kt + 1 < nk) {
            int nb = 1 - cur;
            As[nb][kseg+0][ar]=pa0.x; As[nb][kseg+1][ar]=pa0.y; As[nb][kseg+2][ar]=pa0.z; As[nb][kseg+3][ar]=pa0.w;
            As[nb][kseg+4][ar]=pa1.x; As[nb][kseg+5][ar]=pa1.y; As[nb][kseg+6][ar]=pa1.z; As[nb][kseg+7][ar]=pa1.w;
            #pragma unroll
            for (int j = 0; j < 8; j++) Bs[nb][br][bc0+j] = pb[j];
        }
        __syncthreads();
    }
    #pragma unroll
    for (int i = 0; i < 8; i++) {
        int r = rowBase + ((i < 4) ? (tr*4 + i) : (64 + tr*4 + i - 4));
        if (r >= M) continue;
        #pragma unroll
        for (int j = 0; j < 8; j++) {
            int c = colBase + ((j < 4) ? (tc*4 + j) : (64 + tc*4 + j - 4));
            if (c >= N) continue;
            float v = acc[i][j];
            if (ebias) {
                v += ebias[c];
                if (erelu) v = fmaxf(v, 0.f);
                if (eres) v += eres[(size_t)r*N + c];
            }
            C[(size_t)r*N + c] = v;
        }
    }
}

// ---------------------------------------------------------------------------
// TF32 tensor-core GEMM (Z@wt): C = relu(A@B + ebias) + eres.
// M%128==0, N==128, K%16==0.
// ---------------------------------------------------------------------------
__device__ __forceinline__ unsigned f2tf32(float f){
    unsigned r;
    asm("cvt.rna.tf32.f32 %0, %1;" : "=r"(r) : "f"(f));
    return r;
}

__global__ void __launch_bounds__(256)
k_gemm_tf32(const float* __restrict__ A, const float* __restrict__ B,
            float* __restrict__ C, int M, int N, int K,
            const float* __restrict__ ebias, const float* __restrict__ eres){
    __shared__ float As[2][16][132];
    __shared__ float Bs[2][16][132];
    int tid = threadIdx.x;                 // 256 threads = 8 warps (2m x 4n)
    int lane = tid & 31, warp = tid >> 5;
    int wm = (warp & 1) * 64;
    int wn = (warp >> 1) * 32;
    int rowBase = blockIdx.y*128, colBase = blockIdx.x*128;
    int ar = tid >> 1, kseg = (tid & 1) * 8;
    int br = tid >> 4, bc0 = (tid & 15) * 8;
    int gq = lane >> 2, tg = lane & 3;
    float acc[4][4][4];
    #pragma unroll
    for (int i=0;i<4;i++)
        #pragma unroll
        for (int j=0;j<4;j++)
            #pragma unroll
            for (int q=0;q<4;q++) acc[i][j][q]=0.f;

    int nk = K / 16;
    float4 pa0, pa1, pb0, pb1;
    {
        const float* Ar = A + (size_t)(rowBase+ar)*K + kseg;
        pa0 = *reinterpret_cast<const float4*>(Ar);
        pa1 = *reinterpret_cast<const float4*>(Ar + 4);
        const float* Br = B + (size_t)br*N + colBase + bc0;
        pb0 = *reinterpret_cast<const float4*>(Br);
        pb1 = *reinterpret_cast<const float4*>(Br + 4);
    }
    As[0][kseg+0][ar]=pa0.x; As[0][kseg+1][ar]=pa0.y; As[0][kseg+2][ar]=pa0.z; As[0][kseg+3][ar]=pa0.w;
    As[0][kseg+4][ar]=pa1.x; As[0][kseg+5][ar]=pa1.y; As[0][kseg+6][ar]=pa1.z; As[0][kseg+7][ar]=pa1.w;
    Bs[0][br][bc0+0]=pb0.x; Bs[0][br][bc0+1]=pb0.y; Bs[0][br][bc0+2]=pb0.z; Bs[0][br][bc0+3]=pb0.w;
    Bs[0][br][bc0+4]=pb1.x; Bs[0][br][bc0+5]=pb1.y; Bs[0][br][bc0+6]=pb1.z; Bs[0][br][bc0+7]=pb1.w;
    __syncthreads();

    for (int kt = 0; kt < nk; kt++) {
        int cur = kt & 1;
        if (kt + 1 < nk) {
            int k0 = (kt+1)*16;
            const float* Ar = A + (size_t)(rowBase+ar)*K + k0 + kseg;
            pa0 = *reinterpret_cast<const float4*>(Ar);
            pa1 = *reinterpret_cast<const float4*>(Ar + 4);
            const float* Br = B + (size_t)(k0+br)*N + colBase + bc0;
            pb0 = *reinterpret_cast<const float4*>(Br);
            pb1 = *reinterpret_cast<const float4*>(Br + 4);
        }
        #pragma unroll
        for (int k8 = 0; k8 < 16; k8 += 8) {
            unsigned a[4][4], b[4][2];
            #pragma unroll
            for (int i = 0; i < 4; i++) {
                int mr = wm + i*16 + gq;
                a[i][0] = f2tf32(As[cur][k8+tg][mr]);
                a[i][1] = f2tf32(As[cur][k8+tg][mr+8]);
                a[i][2] = f2tf32(As[cur][k8+4+tg][mr]);
                a[i][3] = f2tf32(As[cur][k8+4+tg][mr+8]);
            }
            #pragma unroll
            for (int j = 0; j < 4; j++) {
                int nc = wn + j*8 + gq;
                b[j][0] = f2tf32(Bs[cur][k8+tg][nc]);
                b[j][1] = f2tf32(Bs[cur][k8+4+tg][nc]);
            }
            #pragma unroll
            for (int i = 0; i < 4; i++)
                #pragma unroll
                for (int j = 0; j < 4; j++) {
                    asm volatile(
                        "mma.sync.aligned.m16n8k8.row.col.f32.tf32.tf32.f32 "
                        "{%0,%1,%2,%3}, {%4,%5,%6,%7}, {%8,%9}, {%0,%1,%2,%3};"
                        : "+f"(acc[i][j][0]), "+f"(acc[i][j][1]),
                          "+f"(acc[i][j][2]), "+f"(acc[i][j][3])
                        : "r"(a[i][0]), "r"(a[i][1]), "r"(a[i][2]), "r"(a[i][3]),
                          "r"(b[j][0]), "r"(b[j][1]));
                }
        }
        if (kt + 1 < nk) {
            int nb = 1 - cur;
            As[nb][kseg+0][ar]=pa0.x; As[nb][kseg+1][ar]=pa0.y; As[nb][kseg+2][ar]=pa0.z; As[nb][kseg+3][ar]=pa0.w;
            As[nb][kseg+4][ar]=pa1.x; As[nb][kseg+5][ar]=pa1.y; As[nb][kseg+6][ar]=pa1.z; As[nb][kseg+7][ar]=pa1.w;
            Bs[nb][br][bc0+0]=pb0.x; Bs[nb][br][bc0+1]=pb0.y; Bs[nb][br][bc0+2]=pb0.z; Bs[nb][br][bc0+3]=pb0.w;
            Bs[nb][br][bc0+4]=pb1.x; Bs[nb][br][bc0+5]=pb1.y; Bs[nb][br][bc0+6]=pb1.z; Bs[nb][br][bc0+7]=pb1.w;
        }
        __syncthreads();
    }
    #pragma unroll
    for (int i = 0; i < 4; i++) {
        int r0 = rowBase + wm + i*16 + gq;
        #pragma unroll
        for (int j = 0; j < 4; j++) {
            int c0 = colBase + wn + j*8 + 2*tg;
            float v0 = fmaxf(acc[i][j][0] + ebias[c0],   0.f) + eres[(size_t)r0*N + c0];
            float v1 = fmaxf(acc[i][j][1] + ebias[c0+1], 0.f) + eres[(size_t)r0*N + c0 + 1];
            float v2 = fmaxf(acc[i][j][2] + ebias[c0],   0.f) + eres[(size_t)(r0+8)*N + c0];
            float v3 = fmaxf(acc[i][j][3] + ebias[c0+1], 0.f) + eres[(size_t)(r0+8)*N + c0 + 1];
            C[(size_t)r0*N + c0]         = v0;
            C[(size_t)r0*N + c0 + 1]     = v1;
            C[(size_t)(r0+8)*N + c0]     = v2;
            C[(size_t)(r0+8)*N + c0 + 1] = v3;
        }
    }
}

// ---------------------------------------------------------------------------
// TF32 tensor-core GEMM, N=64 (GCN1): C = A@B. M%128==0, K%16==0, N==64.
// ---------------------------------------------------------------------------
__global__ void __launch_bounds__(256)
k_gemm_tf32_64(const float* __restrict__ A, const float* __restrict__ B,
               float* __restrict__ C, int M, int K){
    __shared__ float As[2][16][132];
    __shared__ float Bs[2][16][68];
    int tid = threadIdx.x;
    int lane = tid & 31, warp = tid >> 5;
    int wm = (warp & 3) * 32;
    int wn = (warp >> 2) * 32;
    int rowBase = blockIdx.x*128;
    int ar = tid >> 1, kseg = (tid & 1) * 8;
    int br = tid >> 4, bc0 = (tid & 15) * 4;
    int gq = lane >> 2, tg = lane & 3;
    float acc[2][4][4];
    #pragma unroll
    for (int i=0;i<2;i++)
        #pragma unroll
        for (int j=0;j<4;j++)
            #pragma unroll
            for (int q=0;q<4;q++) acc[i][j][q]=0.f;

    int nk = K / 16;
    float4 pa0, pa1, pb0;
    {
        const float* Ar = A + (size_t)(rowBase+ar)*K + kseg;
        pa0 = *reinterpret_cast<const float4*>(Ar);
        pa1 = *reinterpret_cast<const float4*>(Ar + 4);
        pb0 = *reinterpret_cast<const float4*>(&B[(size_t)br*64 + bc0]);
    }
    As[0][kseg+0][ar]=pa0.x; As[0][kseg+1][ar]=pa0.y; As[0][kseg+2][ar]=pa0.z; As[0][kseg+3][ar]=pa0.w;
    As[0][kseg+4][ar]=pa1.x; As[0][kseg+5][ar]=pa1.y; As[0][kseg+6][ar]=pa1.z; As[0][kseg+7][ar]=pa1.w;
    Bs[0][br][bc0+0]=pb0.x; Bs[0][br][bc0+1]=pb0.y; Bs[0][br][bc0+2]=pb0.z; Bs[0][br][bc0+3]=pb0.w;
    __syncthreads();

    for (int kt = 0; kt < nk; kt++) {
        int cur = kt & 1;
        if (kt + 1 < nk) {
            int k0 = (kt+1)*16;
            const float* Ar = A + (size_t)(rowBase+ar)*K + k0 + kseg;
            pa0 = *reinterpret_cast<const float4*>(Ar);
            pa1 = *reinterpret_cast<const float4*>(Ar + 4);
            pb0 = *reinterpret_cast<const float4*>(&B[(size_t)(k0+br)*64 + bc0]);
        }
        #pragma unroll
        for (int k8 = 0; k8 < 16; k8 += 8) {
            unsigned a[2][4], b[4][2];
            #pragma unroll
            for (int i = 0; i < 2; i++) {
                int mr = wm + i*16 + gq;
                a[i][0] = f2tf32(As[cur][k8+tg][mr]);
                a[i][1] = f2tf32(As[cur][k8+tg][mr+8]);
                a[i][2] = f2tf32(As[cur][k8+4+tg][mr]);
                a[i][3] = f2tf32(As[cur][k8+4+tg][mr+8]);
            }
            #pragma unroll
            for (int j = 0; j < 4; j++) {
                int nc = wn + j*8 + gq;
                b[j][0] = f2tf32(Bs[cur][k8+tg][nc]);
                b[j][1] = f2tf32(Bs[cur][k8+4+tg][nc]);
            }
            #pragma unroll
            for (int i = 0; i < 2; i++)
                #pragma unroll
                for (int j = 0; j < 4; j++) {
                    asm volatile(
                        "mma.sync.aligned.m16n8k8.row.col.f32.tf32.tf32.f32 "
                        "{%0,%1,%2,%3}, {%4,%5,%6,%7}, {%8,%9}, {%0,%1,%2,%3};"
                        : "+f"(acc[i][j][0]), "+f"(acc[i][j][1]),
                          "+f"(acc[i][j][2]), "+f"(acc[i][j][3])
                        : "r"(a[i][0]), "r"(a[i][1]), "r"(a[i][2]), "r"(a[i][3]),
                          "r"(b[j][0]), "r"(b[j][1]));
                }
        }
        if (kt + 1 < nk) {
            int nb = 1 - cur;
            As[nb][kseg+0][ar]=pa0.x; As[nb][kseg+1][ar]=pa0.y; As[nb][kseg+2][ar]=pa0.z; As[nb][kseg+3][ar]=pa0.w;
            As[nb][kseg+4][ar]=pa1.x; As[nb][kseg+5][ar]=pa1.y; As[nb][kseg+6][ar]=pa1.z; As[nb][kseg+7][ar]=pa1.w;
            Bs[nb][br][bc0+0]=pb0.x; Bs[nb][br][bc0+1]=pb0.y; Bs[nb][br][bc0+2]=pb0.z; Bs[nb][br][bc0+3]=pb0.w;
        }
        __syncthreads();
    }
    #pragma unroll
    for (int i = 0; i < 2; i++) {
        int r0 = rowBase + wm + i*16 + gq;
        #pragma unroll
        for (int j = 0; j < 4; j++) {
            int c0 = wn + j*8 + 2*tg;
            C[(size_t)r0*64 + c0]         = acc[i][j][0];
            C[(size_t)r0*64 + c0 + 1]     = acc[i][j][1];
            C[(size_t)(r0+8)*64 + c0]     = acc[i][j][2];
            C[(size_t)(r0+8)*64 + c0 + 1] = acc[i][j][3];
        }
    }
}

// ---------------------------------------------------------------------------
// TopK: score + single-block radix select
// ---------------------------------------------------------------------------
__global__ void k_score(const float* __restrict__ h, const float* __restrict__ w,
                        float* score, int n, int F){
    __shared__ float red[256];
    __shared__ float s_wni;
    float s = 0;
    for (int i = threadIdx.x; i < F; i += 256) { float v = w[i]; s += v*v; }
    red[threadIdx.x] = s; __syncthreads();
    for (int o = 128; o; o >>= 1) {
        if (threadIdx.x < o) red[threadIdx.x] += red[threadIdx.x+o];
        __syncthreads();
    }
    if (threadIdx.x == 0) s_wni = rsqrtf(red[0]);
    __syncthreads();
    int wrp = threadIdx.x >> 5, lane = threadIdx.x & 31;
    int node = blockIdx.x*8 + wrp;
    if (node >= n) return;
    const float* r = h + (size_t)node*F;
    float d = 0;
    for (int c = lane; c < F; c += 32) d += r[c]*w[c];
    #pragma unroll
    for (int o = 16; o; o >>= 1) d += __shfl_down_sync(0xFFFFFFFFu, d, o);
    if (!lane) score[node] = tanhf(d * s_wni);
}

__device__ __forceinline__ unsigned fkey(float f){
    unsigned u = __float_as_uint(f);
    return (u & 0x80000000u) ? ~u : (u | 0x80000000u);
}

// n must be a multiple of 4
__global__ void k_select(const float* __restrict__ score, int n, int K,
                         int* __restrict__ keep, int* __restrict__ nid, int* ezero){
    __shared__ unsigned hist[256];
    __shared__ int warpsum[32];
    __shared__ unsigned sh_prefix; __shared__ int sh_krem;
    __shared__ int sh_run;
    int tid = threadIdx.x;                     // 1024 threads
    if (tid == 0) { sh_prefix = 0u; sh_krem = K; if (ezero) *ezero = 0; }
    __syncthreads();
    for (int pass = 0; pass < 4; pass++) {
        if (tid < 256) hist[tid] = 0u;
        __syncthreads();
        int shift = 24 - 8*pass;
        unsigned pfx = sh_prefix;
        unsigned hm = (pass > 0) ? (0xFFFFFFFFu << (shift+8)) : 0u;
        for (int b = tid*4; b < n; b += 4096) {
            float4 v = *reinterpret_cast<const float4*>(score + b);
            unsigned k0 = fkey(v.x), k1 = fkey(v.y), k2 = fkey(v.z), k3 = fkey(v.w);
            if ((k0 & hm) == (pfx & hm)) atomicAdd(&hist[(k0 >> shift) & 0xFFu], 1u);
            if ((k1 & hm) == (pfx & hm)) atomicAdd(&hist[(k1 >> shift) & 0xFFu], 1u);
            if ((k2 & hm) == (pfx & hm)) atomicAdd(&hist[(k2 >> shift) & 0xFFu], 1u);
            if ((k3 & hm) == (pfx & hm)) atomicAdd(&hist[(k3 >> shift) & 0xFFu], 1u);
        }
        __syncthreads();
        if (tid == 0) {
            unsigned k = (unsigned)sh_krem, cum = 0; int b = 0;
            for (int i = 255; i >= 0; i--) {
                unsigned c = hist[i];
                if (cum + c >= k) { b = i; break; }
                cum += c;
            }
            sh_prefix = pfx | ((unsigned)b << shift);
            sh_krem = (int)(k - cum);
        }
        __syncthreads();
    }
    unsigned prefix = sh_prefix; int krem = sh_krem;
    if (tid == 0) sh_run = 0;
    __syncthreads();
    for (int base = 0; base < n; base += 4096) {
        int i0 = base + tid*4;
        int pk[4]; int s = 0;
        unsigned kk[4];
        if (i0 < n) {
            float4 v = *reinterpret_cast<const float4*>(score + i0);
            kk[0] = fkey(v.x); kk[1] = fkey(v.y); kk[2] = fkey(v.z); kk[3] = fkey(v.w);
            #pragma unroll
            for (int j = 0; j < 4; j++) {
                int g = (kk[j] > prefix) ? 1 : 0;
                int t = (kk[j] == prefix) ? 1 : 0;
                pk[j] = (g << 16) | t;
                s += pk[j];
            }
        } else { pk[0]=pk[1]=pk[2]=pk[3]=0; }
        int tot;
        int incl = blk_scan_incl(s, tid, warpsum, &tot);
        int run = sh_run + incl - s;
        if (i0 < n) {
            #pragma unroll
            for (int j = 0; j < 4; j++) {
                int g_before = run >> 16, t_before = run & 0xFFFF;
                int g = pk[j] >> 16, t = pk[j] & 0xFFFF;
                int kp = g | (t && (t_before < krem));
                keep[i0+j] = kp;
                nid[i0+j]  = g_before + (t_before < krem ? t_before : krem);
                run += pk[j];
            }
        }
        __syncthreads();
        if (tid == 0) sh_run += tot;
        __syncthreads();
    }
}

__global__ void k_pool_gather(const float* __restrict__ h, const float* __restrict__ score,
                              const int* __restrict__ keep, const int* __restrict__ nid,
                              float* __restrict__ out, int n, int F){
    int i = blockIdx.x*blockDim.x + threadIdx.x;
    if (i >= n*F) return;
    int node = i / F, c = i % F;
    if (keep[node]) out[(size_t)nid[node]*F + c] = h[i] * score[node];
}

__global__ void k_ecompact(const int* __restrict__ src, const int* __restrict__ dst,
                           const int* __restrict__ keep, const int* __restrict__ nid,
                           const int* pE, int Emax, int* __restrict__ ns,
                           int* __restrict__ nd, int* cntOut, int* deg){
    int e = blockIdx.x*blockDim.x + threadIdx.x;
    if (e >= Emax) return;
    int E = pE ? *pE : Emax;
    if (e >= E) return;
    int s = src[e], d = dst[e];
    if (keep[s] && keep[d]) {
        int j = atomicAdd(cntOut, 1);
        int nsd = nid[s], ndd = nid[d];
        ns[j] = nsd; nd[j] = ndd;
        atomicAdd(&deg[ndd], 1);
    }
}

// ---------------------------------------------------------------------------
// GAT
// ---------------------------------------------------------------------------
__device__ __forceinline__ float lrelu(float x){ return x > 0.f ? x : 0.2f*x; }

__global__ void k_gat_va(const float* __restrict__ gw, const float* __restrict__ as,
                         const float* __restrict__ ad, float* __restrict__ va){
    int t = blockIdx.x*blockDim.x + threadIdx.x;
    int w = t >> 5, lane = t & 31;
    if (w >= FIN*16) return;
    int k = w >> 4, col = w & 15;
    int h = col & 7;
    const float* avec = ((col < 8) ? as : ad) + h*H2c;
    const float* grow = gw + (size_t)k*(HEADSc*H2c) + h*H2c;
    float s = 0;
    for (int c = lane; c < H2c; c += 32) s += grow[c]*avec[c];
    #pragma unroll
    for (int o = 16; o; o >>= 1) s += __shfl_down_sync(0xFFFFFFFFu, s, o);
    if (!lane) va[k*16 + col] = s;
}

// reshape: wt[h*128+k, c] = gw[k, h*128+c]  (wt is 1024 x 128)
__global__ void k_build_wt(const float* __restrict__ gw, float* __restrict__ wt){
    int t = blockIdx.x*blockDim.x + threadIdx.x;
    if (t >= HEADSc*H2c*H2c) return;
    int i = t >> 7, c = t & 127;
    int h = i >> 7, k = i & 127;
    wt[t] = gw[(size_t)k*(HEADSc*H2c) + h*H2c + c];
}

__global__ void k_gat_att(const int* __restrict__ rowptr, const int* __restrict__ csr,
                          const float* __restrict__ alad, float* __restrict__ att,
                          float* __restrict__ attself, int n){
    int t = blockIdx.x*blockDim.x + threadIdx.x;
    int node = t >> 3, h = t & 7;
    if (node >= n) return;
    int e0 = rowptr[node], e1 = rowptr[node+1];
    float add = alad[node*16 + 8 + h];
    float selfv = lrelu(alad[node*16 + h] + add);
    float m = selfv;
    for (int p = e0; p < e1; p++) {
        int s = csr[p];
        m = fmaxf(m, lrelu(alad[s*16 + h] + add));
    }
    float dn = expf(selfv - m);
    for (int p = e0; p < e1; p++) {
        int s = csr[p];
        float ex = expf(lrelu(alad[s*16 + h] + add) - m);
        att[p*8 + h] = ex;
        dn += ex;
    }
    float inv = 0.125f / dn;
    for (int p = e0; p < e1; p++) att[p*8 + h] *= inv;
    attself[node*8 + h] = expf(selfv - m) * inv;
}

// warp per node: z[d, h*128 + f] = attself_h*hp2[d,f] + sum_e att_h*hp2[s,f]
__global__ void k_gat_gather_z(const int* __restrict__ rowptr, const int* __restrict__ csr,
                               const float* __restrict__ hp2, const float* __restrict__ att,
                               const float* __restrict__ attself,
                               float* __restrict__ Z, int n){
    int t = blockIdx.x*blockDim.x + threadIdx.x;
    int w = t >> 5, lane = t & 31;
    if (w >= n) return;
    int e0 = rowptr[w], e1 = rowptr[w+1];
    float z[32];
    #pragma unroll
    for (int j = 0; j < 32; j++) z[j] = 0.f;
    {
        float av = (lane < 8) ? attself[w*8 + lane] : 0.f;
        const float* hr = hp2 + (size_t)w*H2c;
        float x0 = hr[lane], x1 = hr[lane+32], x2 = hr[lane+64], x3 = hr[lane+96];
        #pragma unroll
        for (int h = 0; h < HEADSc; h++) {
            float a = __shfl_sync(0xFFFFFFFFu, av, h);
            z[h*4+0] += a*x0; z[h*4+1] += a*x1; z[h*4+2] += a*x2; z[h*4+3] += a*x3;
        }
    }
    for (int p = e0; p < e1; p++) {
        float av = (lane < 8) ? att[p*8 + lane] : 0.f;
        const float* hr = hp2 + (size_t)csr[p]*H2c;
        float x0 = hr[lane], x1 = hr[lane+32], x2 = hr[lane+64], x3 = hr[lane+96];
        #pragma unroll
        for (int h = 0; h < HEADSc; h++) {
            float a = __shfl_sync(0xFFFFFFFFu, av, h);
            z[h*4+0] += a*x0; z[h*4+1] += a*x1; z[h*4+2] += a*x2; z[h*4+3] += a*x3;
        }
    }
    float* zr = Z + (size_t)w*(HEADSc*H2c);
    #pragma unroll
    for (int h = 0; h < HEADSc; h++) {
        zr[h*H2c + lane]      = z[h*4+0];
        zr[h*H2c + lane + 32] = z[h*4+1];
        zr[h*H2c + lane + 64] = z[h*4+2];
        zr[h*H2c + lane + 96] = z[h*4+3];
    }
}

// ---------------------------------------------------------------------------
// GCN1 gather
// ---------------------------------------------------------------------------
__global__ void k_gcn_gather(const int* __restrict__ rowptr, const int* __restrict__ csr,
                             const float* __restrict__ y, const float* __restrict__ dinv,
                             const float* __restrict__ b, float* __restrict__ o,
                             int n, int C, int relu){
    int t = blockIdx.x*blockDim.x + threadIdx.x;
    int w = t >> 5, lane = t & 31;
    if (w >= n) return;
    int e0 = rowptr[w], e1 = rowptr[w+1];
    float dd = dinv[w];
    float a0 = 0.f, a1 = 0.f;
    bool has2 = (lane + 32) < C;
    for (int p = e0; p < e1; p++) {
        int s = csr[p];
        float ds = dinv[s];
        a0 += ds * y[(size_t)s*C + lane];
        if (has2) a1 += ds * y[(size_t)s*C + lane + 32];
    }
    float v0 = dd*a0 + dd*dd*y[(size_t)w*C + lane] + b[lane];
    o[(size_t)w*C + lane] = relu ? fmaxf(v0, 0.f) : v0;
    if (has2) {
        float v1 = dd*a1 + dd*dd*y[(size_t)w*C + lane + 32] + b[lane+32];
        o[(size_t)w*C + lane + 32] = relu ? fmaxf(v1, 0.f) : v1;
    }
}

// ---------------------------------------------------------------------------
// Collapsed GCN2 + global mean + log_softmax
// ---------------------------------------------------------------------------
__global__ void k_wsum_init(const float* __restrict__ dinv, float* __restrict__ acc,
                            float* __restrict__ r, int n){
    int i = blockIdx.x*blockDim.x + threadIdx.x;
    if (i < n) acc[i] = dinv[i];
    if (i < H1c) r[i] = 0.f;
}
__global__ void k_wsum_edge(const int* __restrict__ src, const int* __restrict__ dst,
                            const float* __restrict__ dinv, float* __restrict__ acc,
                            const int* pE, int Emax){
    int e = blockIdx.x*blockDim.x + threadIdx.x;
    if (e >= Emax) return;
    if (e >= *pE) return;
    atomicAdd(&acc[src[e]], dinv[dst[e]]);
}
__global__ void k_wcolsum(const float* __restrict__ o1, const float* __restrict__ dinv,
                          const float* __restrict__ acc, float* __restrict__ r, int n){
    __shared__ float sh[H1c];
    int tid = threadIdx.x;                 // 256 threads
    if (tid < H1c) sh[tid] = 0.f;
    __syncthreads();
    int lane = tid & 31;
    int gw = (blockIdx.x*256 + tid) >> 5;
    int nw = (gridDim.x*256) >> 5;
    float a0 = 0.f, a1 = 0.f;
    for (int row = gw; row < n; row += nw) {
        float wv = dinv[row]*acc[row];
        a0 += wv * o1[(size_t)row*H1c + lane];
        a1 += wv * o1[(size_t)row*H1c + lane + 32];
    }
    atomicAdd(&sh[lane], a0);
    atomicAdd(&sh[lane + 32], a1);
    __syncthreads();
    if (tid < H1c) atomicAdd(&r[tid], sh[tid]);
}
__global__ void k_final(const float* __restrict__ r, const float* __restrict__ g2w,
                        const float* __restrict__ b, float* __restrict__ out){
    __shared__ float gv[NCc];
    int tid = threadIdx.x;                 // 64 threads
    if (tid < NCc) {
        float s = 0.f;
        for (int f = 0; f < H1c; f++) s += r[f]*g2w[f*NCc + tid];
        gv[tid] = s / (float)K2c + b[tid];
    }
    __syncthreads();
    if (tid == 0) {
        float mxv = -1e30f;
        for (int c = 0; c < NCc; c++) mxv = fmaxf(mxv, gv[c]);
        float s = 0;
        for (int c = 0; c < NCc; c++) s += expf(gv[c] - mxv);
        float l = logf(s);
        for (int c = 0; c < NCc; c++) out[c] = gv[c] - mxv - l;
    }
}

// ---------------------------------------------------------------------------
// Host side
// ---------------------------------------------------------------------------
static void gemm_launch_s(cudaStream_t st, const float* A, const float* B,
                          const float* B2, const float* B3, float* C,
                          int M, int N, int K, int Nh,
                          const float* ebias = nullptr, const float* eres = nullptr,
                          int erelu = 0){
    dim3 grid(CDIV(N, GBN), CDIV(M, GBM));
    k_gemm<<<grid, 256, 0, st>>>(A, B, B2, B3, C, M, N, K, Nh, ebias, eres, erelu);
}

extern "C" void kernel_launch(void* const* d_in, const int* in_sizes, int n_in,
                              void* d_out, int out_size){
    const float* x    = (const float*)d_in[0];
    const int*   ei   = (const int*)  d_in[1];
    const float* s1wl = (const float*)d_in[3];
    const float* s1bl = (const float*)d_in[4];
    const float* s1wr = (const float*)d_in[5];
    const float* r1w  = (const float*)d_in[6];
    const float* r1b  = (const float*)d_in[7];
    const float* p1w  = (const float*)d_in[8];
    const float* s2wl = (const float*)d_in[9];
    const float* s2bl = (const float*)d_in[10];
    const float* s2wr = (const float*)d_in[11];
    const float* r2w  = (const float*)d_in[12];
    const float* r2b  = (const float*)d_in[13];
    const float* p2w  = (const float*)d_in[14];
    const float* gw   = (const float*)d_in[15];
    const float* gas  = (const float*)d_in[16];
    const float* gad  = (const float*)d_in[17];
    const float* gb   = (const float*)d_in[18];
    const float* g1w  = (const float*)d_in[19];
    const float* g1b  = (const float*)d_in[20];
    const float* g2w  = (const float*)d_in[21];
    const float* g2b  = (const float*)d_in[22];
    float* out = (float*)d_out;

    const int* src0 = ei;
    const int* dst0 = ei + Ee;

    float *aggr, *gP, *gQR, *h1, *hp1, *h2, *hp2, *Z, *wt, *va, *alad, *att, *attself;
    float *gin, *y1, *o1, *accv, *rvec, *dinv, *score;
    int *cnt, *rowptr, *wp, *csr, *keep, *nid, *src1, *dst1, *src2, *dst2, *Ecnt;
    cudaGetSymbolAddress((void**)&aggr,    d_aggr);
    cudaGetSymbolAddress((void**)&cnt,     d_cnt);
    cudaGetSymbolAddress((void**)&rowptr,  d_rowptr);
    cudaGetSymbolAddress((void**)&wp,      d_wp);
    cudaGetSymbolAddress((void**)&csr,     d_csr);
    cudaGetSymbolAddress((void**)&gP,      d_gP);
    cudaGetSymbolAddress((void**)&gQR,     d_gQR);
    cudaGetSymbolAddress((void**)&h1,      d_h1);
    cudaGetSymbolAddress((void**)&hp1,     d_hp1);
    cudaGetSymbolAddress((void**)&h2,      d_h2);
    cudaGetSymbolAddress((void**)&hp2,     d_hp2);
    cudaGetSymbolAddress((void**)&Z,       d_z);
    cudaGetSymbolAddress((void**)&wt,      d_wt);
    cudaGetSymbolAddress((void**)&va,      d_va);
    cudaGetSymbolAddress((void**)&alad,    d_alad);
    cudaGetSymbolAddress((void**)&att,     d_att);
    cudaGetSymbolAddress((void**)&attself, d_attself);
    cudaGetSymbolAddress((void**)&gin,     d_gin);
    cudaGetSymbolAddress((void**)&y1,      d_y1);
    cudaGetSymbolAddress((void**)&o1,      d_o1);
    cudaGetSymbolAddress((void**)&accv,    d_acc);
    cudaGetSymbolAddress((void**)&rvec,    d_rvec);
    cudaGetSymbolAddress((void**)&dinv,    d_dinv);
    cudaGetSymbolAddress((void**)&score,   d_score);
    cudaGetSymbolAddress((void**)&keep,    d_keep);
    cudaGetSymbolAddress((void**)&nid,     d_nid);
    cudaGetSymbolAddress((void**)&src1,    d_src1);
    cudaGetSymbolAddress((void**)&dst1,    d_dst1);
    cudaGetSymbolAddress((void**)&src2,    d_src2);
    cudaGetSymbolAddress((void**)&dst2,    d_dst2);
    cudaGetSymbolAddress((void**)&Ecnt,    d_Ecnt);

    static cudaStream_t s1 = nullptr, s2 = nullptr;
    static cudaEvent_t  ev[10];
    if (!s1) {
        cudaStreamCreate(&s1);
        cudaStreamCreate(&s2);
        for (int i = 0; i < 10; i++) cudaEventCreateWithFlags(&ev[i], cudaEventDisableTiming);
    }
    cudaStream_t M = 0;

    const int ET_GRID = CDIV(Ee, 256);

    // ===== Phase A: SAGE1 GEMM (M) || CSR1 (s1) || weight prep (s2) =====
    cudaEventRecord(ev[0], M);
    cudaStreamWaitEvent(s1, ev[0], 0);
    cudaStreamWaitEvent(s2, ev[0], 0);
    gemm_launch_s(M, x, s1wl, s1wr, r1w, gQR, Nn, 3*H1c, FIN, H1c);  // Y=x@[wl|wr|res]
    k_gat_va<<<CDIV(FIN*16*32, 256), 256, 0, s2>>>(gw, gas, gad, va);
    k_build_wt<<<CDIV(HEADSc*H2c*H2c, 256), 256, 0, s2>>>(gw, wt);
    cudaEventRecord(ev[8], s2);                      // va + wt ready
    k_count<<<ET_GRID, 256, 0, s1>>>(dst0, cnt, nullptr, Ee);
    k_exscan<<<1, 1024, 0, s1>>>(cnt, rowptr, wp, Nn, Nn, nullptr);
    k_fill<<<ET_GRID, 256, 0, s1>>>(src0, dst0, wp, csr, nullptr, Ee);
    cudaEventRecord(ev[1], s1);
    cudaStreamWaitEvent(M, ev[1], 0);

    // ===== SAGE1 gather + Pool 1 (M) =====
    k_sage1_gather<<<CDIV(Nn*32, 256), 256, 0, M>>>(rowptr, csr, gQR, s1bl, r1b, h1, Nn);
    k_score<<<CDIV(Nn, 8), 256, 0, M>>>(h1, p1w, score, Nn, H1c);
    k_select<<<1, 1024, 0, M>>>(score, Nn, K1c, keep, nid, Ecnt);

    // ===== Phase C: pool_gather1 (M)  ||  CSR2 chain (s1) =====
    cudaEventRecord(ev[2], M);
    cudaStreamWaitEvent(s1, ev[2], 0);
    k_pool_gather<<<CDIV(Nn*H1c, 256), 256, 0, M>>>(h1, score, keep, nid, hp1, Nn, H1c);
    cudaEventRecord(ev[3], M);                       // hp1 ready
    k_ecompact<<<ET_GRID, 256, 0, s1>>>(src0, dst0, keep, nid, nullptr, Ee,
                                        src1, dst1, Ecnt, cnt);
    k_exscan<<<1, 1024, 0, s1>>>(cnt, rowptr, wp, K1c, Nn, nullptr);
    k_fill<<<ET_GRID, 256, 0, s1>>>(src1, dst1, wp, csr, Ecnt, Ee);

    // ===== Phase D: QR GEMM (M)  ||  mean_gather + P GEMM (s1) =====
    cudaStreamWaitEvent(s1, ev[3], 0);
    k_mean_gather<<<CDIV(K1c*32, 256), 256, 0, s1>>>(rowptr, csr, hp1, aggr, K1c);
    gemm_launch_s(s1, aggr, s2wl, nullptr, nullptr, gP, K1c, H2c, H1c, 0);
    gemm_launch_s(M, hp1, s2wr, r2w, nullptr, gQR, K1c, 2*H2c, H1c, H2c);
    cudaEventRecord(ev[4], s1);
    cudaStreamWaitEvent(M, ev[4], 0);

    // ===== SAGE2 combine + Pool 2 (M) =====
    k_sage_combine<<<CDIV(K1c*H2c, 256), 256, 0, M>>>(gP, gQR, s2bl, r2b, h2, K1c, H2c);
    k_score<<<CDIV(K1c, 8), 256, 0, M>>>(h2, p2w, score, K1c, H2c);
    k_select<<<1, 1024, 0, M>>>(score, K1c, K2c, keep, nid, Ecnt + 1);

    // ===== Phase F: pool2 + alad (M) || CSR3 (s1) || wsum (s2) =====
    cudaEventRecord(ev[5], M);
    cudaStreamWaitEvent(s1, ev[5], 0);
    k_pool_gather<<<CDIV(K1c*H2c, 256), 256, 0, M>>>(h2, score, keep, nid, hp2, K1c, H2c);
    cudaStreamWaitEvent(M, ev[8], 0);                // va ready
    gemm_launch_s(M, hp2, va, nullptr, nullptr, alad, K2c, 16, H2c, 0);
    k_ecompact<<<ET_GRID, 256, 0, s1>>>(src1, dst1, keep, nid, Ecnt, Ee,
                                        src2, dst2, Ecnt + 1, cnt);
    k_exscan<<<1, 1024, 0, s1>>>(cnt, rowptr, wp, K2c, Nn, dinv);
    cudaEventRecord(ev[6], s1);                      // dinv + counts ready
    k_fill<<<ET_GRID, 256, 0, s1>>>(src2, dst2, wp, csr, Ecnt + 1, Ee);
    cudaEventRecord(ev[9], s1);                      // CSR3 ready
    cudaStreamWaitEvent(s2, ev[6], 0);               // wsum on s2, parallel to fill3
    k_wsum_init<<<CDIV(K2c, 256), 256, 0, s2>>>(dinv, accv, rvec, K2c);
    k_wsum_edge<<<ET_GRID, 256, 0, s2>>>(src2, dst2, dinv, accv, Ecnt + 1, Ee);
    cudaEventRecord(ev[7], s2);                      // wsum ready
    cudaStreamWaitEvent(M, ev[9], 0);

    // ===== GAT (aggregate-then-project, tf32) + GCN1 (tf32) + head (M) =====
    k_gat_att<<<CDIV(K2c*8, 256), 256, 0, M>>>(rowptr, csr, alad, att, attself, K2c);
    k_gat_gather_z<<<CDIV(K2c*32, 256), 256, 0, M>>>(rowptr, csr, hp2, att, attself, Z, K2c);
    {   // gin = relu(Z@wt + gb) + hp2, tf32 tensor cores (12800x128x1024)
        dim3 g(1, K2c/128);
        k_gemm_tf32<<<g, 256, 0, M>>>(Z, wt, gin, K2c, H2c, HEADSc*H2c, gb, hp2);
    }

    k_gemm_tf32_64<<<K2c/128, 256, 0, M>>>(gin, g1w, y1, K2c, H2c);   // y1 = gin@g1w
    k_gcn_gather<<<CDIV(K2c*32, 256), 256, 0, M>>>(rowptr, csr, y1, dinv, g1b, o1, K2c, H1c, 1);

    cudaStreamWaitEvent(M, ev[7], 0);
    k_wcolsum<<<64, 256, 0, M>>>(o1, dinv, accv, rvec, K2c);
    k_final<<<1, 64, 0, M>>>(rvec, g2w, g2b, out);
}